// round 15
// baseline (speedup 1.0000x reference)
#include <cuda_runtime.h>
#include <cuda_bf16.h>
#include <math.h>
#include <stdint.h>

#define N_NODES 20000
#define N_EDGES 320000
#define H 128
#define CUTOFF_R 5.0f
#define PI_F 3.14159265358979323846f

// ========================= scratch (device globals) =========================
__device__ __align__(16) float g_ns[N_NODES * H];
__device__ __align__(16) float g_nv[N_NODES * 3 * H];
__device__ __align__(16) float g_ns1[N_NODES * H];
__device__ __align__(16) float g_nvec1[N_NODES * 3 * H];
__device__ __align__(16) float g_wv[N_NODES * 3 * 2 * H];
__device__ __align__(16) float g_p[N_NODES * 3 * H];
__device__ __align__(16) __nv_bfloat16 g_wpack[11 * 32768];

__device__ int g_deg[N_NODES];      // zero-init; scan() re-zeros after use
__device__ int g_off[N_NODES + 1];
__device__ int g_cur[N_NODES];
__device__ int g_eids[N_EDGES];
__device__ int g_own[N_EDGES];
__device__ int g_ej[N_EDGES];
__device__ float g_distc[N_EDGES];
__device__ float g_evc[N_EDGES * 3];

// ========================= helpers =========================
__device__ __forceinline__ uint32_t smem_u32(const void* p) {
    uint32_t a;
    asm("{ .reg .u64 t; cvta.to.shared.u64 t, %1; cvt.u32.u64 %0, t; }" : "=r"(a) : "l"(p));
    return a;
}
__device__ __forceinline__ float silu_f(float x) { return x / (1.0f + __expf(-x)); }

#define LDSM4(r, addr) \
    asm volatile("ldmatrix.sync.aligned.m8n8.x4.shared.b16 {%0,%1,%2,%3}, [%4];" \
        : "=r"((r)[0]), "=r"((r)[1]), "=r"((r)[2]), "=r"((r)[3]) : "r"(addr))

#define MMA16816(c, a, b) \
    asm volatile("mma.sync.aligned.m16n8k16.row.col.f32.bf16.bf16.f32 " \
        "{%0,%1,%2,%3}, {%4,%5,%6,%7}, {%8,%9}, {%0,%1,%2,%3};" \
        : "+f"((c)[0]), "+f"((c)[1]), "+f"((c)[2]), "+f"((c)[3]) \
        : "r"((a)[0]), "r"((a)[1]), "r"((a)[2]), "r"((a)[3]), "r"((b)[0]), "r"((b)[1]))

// ========================= pack + distributed histogram ======================
__global__ void pack_hist(const float* __restrict__ Wn, const float* __restrict__ We,
                          const float* __restrict__ Wp1, const float* __restrict__ Wc,
                          const float* __restrict__ Wf, const float* __restrict__ Wv,
                          const float* __restrict__ Wp2,
                          const int* __restrict__ ei) {
    const int tid = threadIdx.x;
    int b = blockIdx.x;
    {
        const int per_blk = (N_EDGES + 21) / 22;
        int beg = b * per_blk;
        int end = min(beg + per_blk, N_EDGES);
        for (int e = beg + tid; e < end; e += 1024)
            atomicAdd(&g_deg[__ldg(ei + e)], 1);
    }
    int tile = b >> 1, half = b & 1;
    const float* W; int ncol, t;
    switch (tile) {
        case 0: W = Wn;  ncol = 128; t = 0; break;
        case 1: W = We;  ncol = 128; t = 0; break;
        case 2: case 3: W = Wp1; ncol = 256; t = tile - 2; break;
        case 4: W = Wc;  ncol = 128; t = 0; break;
        case 5: W = Wf;  ncol = 128; t = 0; break;
        case 6: case 7: W = Wv;  ncol = 256; t = tile - 6; break;
        default: W = Wp2; ncol = 384; t = tile - 8; break;
    }
    uint32_t* dst = (uint32_t*)(g_wpack + (size_t)tile * 32768);
    #pragma unroll
    for (int q = 0; q < 4; q++) {
        int e = half * 4096 + tid * 4 + q;
        int r = e & 7, lane = (e >> 3) & 31, ks = (e >> 8) & 7, wn = e >> 11;
        int n = wn * 32 + (r >> 1) * 8 + (lane >> 2);
        int k = ks * 16 + (r & 1) * 8 + (lane & 3) * 2;
        float v0 = W[(size_t)k * ncol + t * 128 + n];
        float v1 = W[(size_t)(k + 1) * ncol + t * 128 + n];
        __nv_bfloat16 h0 = __float2bfloat16(v0);
        __nv_bfloat16 h1 = __float2bfloat16(v1);
        __nv_bfloat16 l0 = __float2bfloat16(v0 - __bfloat162float(h0));
        __nv_bfloat16 l1 = __float2bfloat16(v1 - __bfloat162float(h1));
        uint32_t hp = (uint32_t)*(uint16_t*)&h0 | ((uint32_t)*(uint16_t*)&h1 << 16);
        uint32_t lp = (uint32_t)*(uint16_t*)&l0 | ((uint32_t)*(uint16_t*)&l1 << 16);
        dst[e] = hp;
        dst[8192 + e] = lp;
    }
}

// single-block exclusive scan (self-cleans g_deg)
__global__ void csr_scan() {
    const int tid = threadIdx.x;
    const int lane = tid & 31, w = tid >> 5;
    __shared__ int wsum[32];
    __shared__ int carry;
    if (tid == 0) carry = 0;
    __syncthreads();
    for (int base = 0; base < N_NODES; base += 1024) {
        int idx = base + tid;
        int v = (idx < N_NODES) ? g_deg[idx] : 0;
        if (idx < N_NODES) g_deg[idx] = 0;
        int s = v;
        #pragma unroll
        for (int o = 1; o < 32; o <<= 1) {
            int t = __shfl_up_sync(0xffffffffu, s, o);
            if (lane >= o) s += t;
        }
        if (lane == 31) wsum[w] = s;
        __syncthreads();
        if (w == 0) {
            int x = wsum[lane];
            #pragma unroll
            for (int o = 1; o < 32; o <<= 1) {
                int t = __shfl_up_sync(0xffffffffu, x, o);
                if (lane >= o) x += t;
            }
            wsum[lane] = x;
        }
        __syncthreads();
        int blockoff = (w > 0) ? wsum[w - 1] : 0;
        int c = carry;
        if (idx < N_NODES) {
            int excl = c + blockoff + s - v;
            g_off[idx] = excl;
            g_cur[idx] = excl;
        }
        int tot = wsum[31];
        __syncthreads();
        if (tid == 0) carry = c + tot;
        __syncthreads();
    }
    if (tid == 0) g_off[N_NODES] = carry;
}

// ========================= shared GEMM plumbing (64-row tiles) ==============
#define ASTRIDE 136
#define CSTRIDE 132
#define A_LO    17408
#define SM_GEMM 34816
#define SM_MEGA 70144

__device__ __forceinline__ void a_split_store(char* smem, int r, int k0, float4 a) {
    __nv_bfloat162 h01 = __float22bfloat162_rn(make_float2(a.x, a.y));
    __nv_bfloat162 h23 = __float22bfloat162_rn(make_float2(a.z, a.w));
    float2 f01 = __bfloat1622float2(h01);
    float2 f23 = __bfloat1622float2(h23);
    __nv_bfloat162 l01 = __float22bfloat162_rn(make_float2(a.x - f01.x, a.y - f01.y));
    __nv_bfloat162 l23 = __float22bfloat162_rn(make_float2(a.z - f23.x, a.w - f23.y));
    uint2 hv, lv;
    hv.x = *(uint32_t*)&h01; hv.y = *(uint32_t*)&h23;
    lv.x = *(uint32_t*)&l01; lv.y = *(uint32_t*)&l23;
    *(uint2*)(smem + (r * ASTRIDE + k0) * 2) = hv;
    *(uint2*)(smem + A_LO + (r * ASTRIDE + k0) * 2) = lv;
}

__device__ __forceinline__ void mma_setup(uint32_t aoff[2], int lane, int warp_m) {
    const int rin = lane & 7, sel = lane >> 3;
    #pragma unroll
    for (int mt = 0; mt < 2; mt++) {
        int row = warp_m * 32 + mt * 16 + (sel & 1) * 8 + rin;
        int col = (sel >> 1) * 8;
        aoff[mt] = (uint32_t)((row * ASTRIDE + col) * 2);
    }
}

__device__ __forceinline__ void zero_acc(float acc[2][4][4]) {
    #pragma unroll
    for (int mt = 0; mt < 2; mt++)
        #pragma unroll
        for (int nt = 0; nt < 4; nt++)
            #pragma unroll
            for (int u = 0; u < 4; u++) acc[mt][nt][u] = 0.f;
}

__device__ __forceinline__ void mma_mainloop(float acc[2][4][4], const uint32_t aoff[2],
                                             uint32_t sb, const uint4* __restrict__ Bp,
                                             int warp_n, int lane) {
    const uint32_t aHi = sb, aLo = sb + A_LO;
    #pragma unroll
    for (int ks = 0; ks < 8; ks++) {
        uint32_t kb = ks * 32;
        uint32_t ah[2][4], al[2][4];
        int idx = ((warp_n * 8 + ks) * 32 + lane) * 2;
        uint4 u0 = __ldg(Bp + idx);
        uint4 u1 = __ldg(Bp + idx + 1);
        uint4 l0 = __ldg(Bp + idx + 2048);
        uint4 l1 = __ldg(Bp + idx + 2049);
        LDSM4(ah[0], aHi + aoff[0] + kb);
        LDSM4(ah[1], aHi + aoff[1] + kb);
        LDSM4(al[0], aLo + aoff[0] + kb);
        LDSM4(al[1], aLo + aoff[1] + kb);
        uint32_t bh[4][2], bl[4][2];
        bh[0][0] = u0.x; bh[0][1] = u0.y; bh[1][0] = u0.z; bh[1][1] = u0.w;
        bh[2][0] = u1.x; bh[2][1] = u1.y; bh[3][0] = u1.z; bh[3][1] = u1.w;
        bl[0][0] = l0.x; bl[0][1] = l0.y; bl[1][0] = l0.z; bl[1][1] = l0.w;
        bl[2][0] = l1.x; bl[2][1] = l1.y; bl[3][0] = l1.z; bl[3][1] = l1.w;
        #pragma unroll
        for (int mt = 0; mt < 2; mt++)
            #pragma unroll
            for (int nt = 0; nt < 4; nt++) {
                MMA16816(acc[mt][nt], ah[mt], bh[nt]);
                MMA16816(acc[mt][nt], ah[mt], bl[nt]);
                MMA16816(acc[mt][nt], al[mt], bh[nt]);
            }
    }
}

// dual-accumulator mainloop: A fragments loaded ONCE for two B matrices
__device__ __forceinline__ void mma_mainloop_dual(
        float accX[2][4][4], float accY[2][4][4], const uint32_t aoff[2],
        uint32_t sb, const uint4* __restrict__ BpX, const uint4* __restrict__ BpY,
        int warp_n, int lane) {
    const uint32_t aHi = sb, aLo = sb + A_LO;
    #pragma unroll
    for (int ks = 0; ks < 8; ks++) {
        uint32_t kb = ks * 32;
        uint32_t ah[2][4], al[2][4];
        int idx = ((warp_n * 8 + ks) * 32 + lane) * 2;
        LDSM4(ah[0], aHi + aoff[0] + kb);
        LDSM4(ah[1], aHi + aoff[1] + kb);
        LDSM4(al[0], aLo + aoff[0] + kb);
        LDSM4(al[1], aLo + aoff[1] + kb);
        {
            uint4 u0 = __ldg(BpX + idx);
            uint4 u1 = __ldg(BpX + idx + 1);
            uint4 l0 = __ldg(BpX + idx + 2048);
            uint4 l1 = __ldg(BpX + idx + 2049);
            uint32_t bh[4][2], bl[4][2];
            bh[0][0] = u0.x; bh[0][1] = u0.y; bh[1][0] = u0.z; bh[1][1] = u0.w;
            bh[2][0] = u1.x; bh[2][1] = u1.y; bh[3][0] = u1.z; bh[3][1] = u1.w;
            bl[0][0] = l0.x; bl[0][1] = l0.y; bl[1][0] = l0.z; bl[1][1] = l0.w;
            bl[2][0] = l1.x; bl[2][1] = l1.y; bl[3][0] = l1.z; bl[3][1] = l1.w;
            #pragma unroll
            for (int mt = 0; mt < 2; mt++)
                #pragma unroll
                for (int nt = 0; nt < 4; nt++) {
                    MMA16816(accX[mt][nt], ah[mt], bh[nt]);
                    MMA16816(accX[mt][nt], ah[mt], bl[nt]);
                    MMA16816(accX[mt][nt], al[mt], bh[nt]);
                }
        }
        {
            uint4 u0 = __ldg(BpY + idx);
            uint4 u1 = __ldg(BpY + idx + 1);
            uint4 l0 = __ldg(BpY + idx + 2048);
            uint4 l1 = __ldg(BpY + idx + 2049);
            uint32_t bh[4][2], bl[4][2];
            bh[0][0] = u0.x; bh[0][1] = u0.y; bh[1][0] = u0.z; bh[1][1] = u0.w;
            bh[2][0] = u1.x; bh[2][1] = u1.y; bh[3][0] = u1.z; bh[3][1] = u1.w;
            bl[0][0] = l0.x; bl[0][1] = l0.y; bl[1][0] = l0.z; bl[1][1] = l0.w;
            bl[2][0] = l1.x; bl[2][1] = l1.y; bl[3][0] = l1.z; bl[3][1] = l1.w;
            #pragma unroll
            for (int mt = 0; mt < 2; mt++)
                #pragma unroll
                for (int nt = 0; nt < 4; nt++) {
                    MMA16816(accY[mt][nt], ah[mt], bh[nt]);
                    MMA16816(accY[mt][nt], ah[mt], bl[nt]);
                    MMA16816(accY[mt][nt], al[mt], bh[nt]);
                }
        }
    }
}

__device__ __forceinline__ void stage_c(float* Cs, const float acc[2][4][4],
                                        int lane, int warp_m, int warp_n) {
    int gid = lane >> 2, tig = lane & 3;
    #pragma unroll
    for (int mt = 0; mt < 2; mt++) {
        int r = warp_m * 32 + mt * 16 + gid;
        #pragma unroll
        for (int nt = 0; nt < 4; nt++) {
            int cc = warp_n * 32 + nt * 8 + tig * 2;
            *(float2*)&Cs[r * CSTRIDE + cc] = make_float2(acc[mt][nt][0], acc[mt][nt][1]);
            *(float2*)&Cs[(r + 8) * CSTRIDE + cc] = make_float2(acc[mt][nt][2], acc[mt][nt][3]);
        }
    }
}

// ========================= GEMM body (modes 0,1,2) ===========================
__device__ __forceinline__ void gemm_body(
        char* smem,
        const float* __restrict__ A, int M,
        const __nv_bfloat16* __restrict__ Bpack,
        const float* __restrict__ bias,
        float* __restrict__ C, int ldc, int mode,
        const float* __restrict__ gamma,
        const float* __restrict__ beta,
        float* __restrict__ aux,
        int row0, int ncoff) {
    const int tid = threadIdx.x;
    const int lane = tid & 31, wid = tid >> 5;
    const int warp_m = wid >> 2, warp_n = wid & 3;
    const uint4* Bp = (const uint4*)Bpack;
    const uint32_t sb = smem_u32(smem);

    {
        int r = tid >> 2, k0 = (tid & 3) * 32;
        int arow = row0 + r;
        bool vr = arow < M;
        const float4* src = (const float4*)(A + (size_t)arow * 128 + k0);
        float4 av[8];
        #pragma unroll
        for (int q = 0; q < 8; q++)
            av[q] = vr ? __ldg(src + q) : make_float4(0.f, 0.f, 0.f, 0.f);

        if (mode >= 1 && vr) {
            float4* dstaux = (float4*)(aux + (size_t)arow * 128 + k0);
            #pragma unroll
            for (int q = 0; q < 8; q++) dstaux[q] = av[q];
        }
        if (mode == 1) {
            float s = 0.f, s2 = 0.f;
            #pragma unroll
            for (int q = 0; q < 8; q++) {
                s  += av[q].x + av[q].y + av[q].z + av[q].w;
                s2 += av[q].x*av[q].x + av[q].y*av[q].y + av[q].z*av[q].z + av[q].w*av[q].w;
            }
            s  += __shfl_xor_sync(0xffffffffu, s, 1);
            s  += __shfl_xor_sync(0xffffffffu, s, 2);
            s2 += __shfl_xor_sync(0xffffffffu, s2, 1);
            s2 += __shfl_xor_sync(0xffffffffu, s2, 2);
            float mu = s * (1.0f / H);
            float var = s2 * (1.0f / H) - mu * mu;
            float inv = rsqrtf(var + 1e-5f);
            #pragma unroll
            for (int q = 0; q < 8; q++) {
                int k = k0 + q * 4;
                float4 gm = __ldg((const float4*)(gamma + k));
                float4 bt = __ldg((const float4*)(beta + k));
                av[q].x = (av[q].x - mu) * inv * gm.x + bt.x;
                av[q].y = (av[q].y - mu) * inv * gm.y + bt.y;
                av[q].z = (av[q].z - mu) * inv * gm.z + bt.z;
                av[q].w = (av[q].w - mu) * inv * gm.w + bt.w;
            }
        }
        #pragma unroll
        for (int q = 0; q < 8; q++)
            a_split_store(smem, r, k0 + q * 4, av[q]);
    }
    __syncthreads();

    float acc[2][4][4];
    zero_acc(acc);
    uint32_t aoff[2];
    mma_setup(aoff, lane, warp_m);
    mma_mainloop(acc, aoff, sb, Bp, warp_n, lane);
    __syncthreads();

    float* Cs = (float*)smem;
    stage_c(Cs, acc, lane, warp_m, warp_n);
    __syncthreads();

    const int r = tid >> 2;
    const int c0g = (tid & 3) * 32;
    const int grow = row0 + r;
    if (grow >= M) return;
    float* dst = C + (size_t)grow * ldc + ncoff + c0g;

    #pragma unroll
    for (int ch = 0; ch < 2; ch++) {
        const int cl = c0g + ch * 16;
        float d[16];
        #pragma unroll
        for (int c = 0; c < 16; c++) d[c] = Cs[r * CSTRIDE + cl + c];
        if (bias) {
            #pragma unroll
            for (int c = 0; c < 16; c++) d[c] += __ldg(bias + cl + c);
        }
        #pragma unroll
        for (int q = 0; q < 4; q++)
            *(float4*)(dst + ch * 16 + 4 * q) =
                make_float4(d[4*q], d[4*q+1], d[4*q+2], d[4*q+3]);
    }
}

#define GB_N  ((N_NODES + 63) / 64)       // 313
#define GB_3N ((3 * N_NODES + 63) / 64)   // 938
#define GB_E  (N_EDGES / 64)              // 5000
#define SCAT_BLKS ((N_EDGES + 255) / 256) // 1250

// ===== merged launch: csr_scatter blocks + gemmA blocks ======================
__global__ __launch_bounds__(256, 4)
void scatter_gemmA(const int* __restrict__ ei,
                   const float* __restrict__ dist,
                   const float* __restrict__ ev,
                   const float* __restrict__ node_scalar,
                   const float* __restrict__ node_vector,
                   const __nv_bfloat16* __restrict__ wpN,
                   const __nv_bfloat16* __restrict__ wpC,
                   const float* __restrict__ b_node,
                   const float* __restrict__ gamma,
                   const float* __restrict__ beta,
                   float* __restrict__ ns, float* __restrict__ nv,
                   float* __restrict__ ns1, float* __restrict__ nvec1) {
    extern __shared__ char smem[];
    int bx = blockIdx.x;
    if (bx < SCAT_BLKS) {
        int e = bx * 256 + threadIdx.x;
        if (e < N_EDGES) {
            int i = ei[e];
            int j = ei[N_EDGES + e];
            int pos = atomicAdd(&g_cur[i], 1);
            g_eids[pos] = e;
            g_own[pos] = i;
            g_ej[pos] = j;
            g_distc[pos] = dist[e];
            g_evc[pos * 3 + 0] = ev[e * 3 + 0];
            g_evc[pos * 3 + 1] = ev[e * 3 + 1];
            g_evc[pos * 3 + 2] = ev[e * 3 + 2];
        }
        return;
    }
    bx -= SCAT_BLKS;
    if (bx < GB_3N) {
        gemm_body(smem, node_vector, 3 * N_NODES, wpC, nullptr,
                  nv, 128, 2, nullptr, nullptr, nvec1, bx * 64, 0);
    } else {
        gemm_body(smem, node_scalar, N_NODES, wpN, b_node,
                  ns, 128, 1, gamma, beta, ns1, (bx - GB_3N) * 64, 0);
    }
}

// ===== combined launch B =====
__global__ __launch_bounds__(256, 4)
void gemmB(const float* __restrict__ nvec1,
           const float* __restrict__ ns1,
           const __nv_bfloat16* __restrict__ wpV,
           const __nv_bfloat16* __restrict__ wpP2,
           const float* __restrict__ b_p2,
           float* __restrict__ wv, float* __restrict__ p) {
    extern __shared__ char smem[];
    int bx = blockIdx.x;
    if (bx < GB_3N * 2) {
        int yt = bx & 1, rb = bx >> 1;
        gemm_body(smem, nvec1, 3 * N_NODES, wpV + (size_t)yt * 32768, nullptr,
                  wv, 256, 0, nullptr, nullptr, nullptr, rb * 64, yt * 128);
    } else {
        int idx = bx - GB_3N * 2;
        int yt = idx % 3, rb = idx / 3;
        gemm_body(smem, ns1, N_NODES, wpP2 + (size_t)yt * 32768, b_p2 + yt * 128,
                  p, 384, 0, nullptr, nullptr, nullptr, rb * 64, yt * 128);
    }
}

// ========================= MEGA message + edge-final (dual-acc, 2 CTAs/SM) ===
__global__ __launch_bounds__(256, 2)
void mega_msg(const float* __restrict__ efeat,
              const __nv_bfloat16* __restrict__ Wedge,
              const __nv_bfloat16* __restrict__ Wp1,
              const __nv_bfloat16* __restrict__ Wf,
              const float* __restrict__ b_edge,
              const float* __restrict__ b_p1,
              const float* __restrict__ b_f,
              const int* __restrict__ eids,
              const int* __restrict__ own,
              const int* __restrict__ ejArr,
              const float* __restrict__ distc,
              const float* __restrict__ alpha,
              const float* __restrict__ evc,
              const float* __restrict__ ns,
              const float* __restrict__ nvec,
              const float* __restrict__ nv_cross,
              float* __restrict__ ns1,
              float* __restrict__ nvec1,
              float* __restrict__ out_edge) {
    extern __shared__ char smem[];
    const int tid = threadIdx.x;
    const int lane = tid & 31, wid = tid >> 5;
    const int warp_m = wid >> 2, warp_n = wid & 3;
    const int row0 = blockIdx.x * 64;
    const uint32_t sb = smem_u32(smem);
    const uint4* BpE = (const uint4*)Wedge;
    const uint4* Bp1a = (const uint4*)Wp1;
    const uint4* Bp1b = (const uint4*)(Wp1 + 32768);
    const uint4* BpF = (const uint4*)Wf;

    float* Cs0 = (float*)(smem + 34816);
    float* As  = (float*)smem;
    int* sOwn = (int*)(smem + 68608);
    int* sEj  = (int*)(smem + 68864);
    int* sEid = (int*)(smem + 69120);
    float* sEv = (float*)(smem + 69376);

    // Phase A: gathered edge_feats rows (streaming), split; meta
    {
        int r = tid >> 2, k0 = (tid & 3) * 32;
        int e = eids[row0 + r];
        const float4* src = (const float4*)(efeat + (size_t)e * 128 + k0);
        float4 av[8];
        #pragma unroll
        for (int q = 0; q < 8; q++) av[q] = __ldcs(src + q);
        #pragma unroll
        for (int q = 0; q < 8; q++) a_split_store(smem, r, k0 + q * 4, av[q]);
    }
    if (tid < 64) {
        sOwn[tid] = own[row0 + tid];
        sEj[tid]  = ejArr[row0 + tid];
        sEid[tid] = eids[row0 + tid];
        sEv[tid * 3 + 0] = evc[(row0 + tid) * 3 + 0];
        sEv[tid * 3 + 1] = evc[(row0 + tid) * 3 + 1];
        sEv[tid * 3 + 2] = evc[(row0 + tid) * 3 + 2];
    }
    __syncthreads();

    uint32_t aoff[2];
    mma_setup(aoff, lane, warp_m);

    // Fused mainloop 1: ef GEMM (W_edge -> accE) + W_f GEMM (-> accF)
    float accE[2][4][4], accF[2][4][4];
    zero_acc(accE);
    zero_acc(accF);
    mma_mainloop_dual(accE, accF, aoff, sb, BpE, BpF, warp_n, lane);
    stage_c(Cs0, accE, lane, warp_m, warp_n);
    __syncthreads();

    // Phase C: per-row msg epilogue (msg back into Cs0)
    {
        const int r = tid >> 2;
        const int c0g = (tid & 3) * 32;
        const int grow = row0 + r;
        int ii = sOwn[r], jj = sEj[r];
        float dd = __ldg(distc + grow);
        float cut = (dd < CUTOFF_R) ? 0.5f * (__cosf(PI_F * dd / CUTOFF_R) + 1.0f) : 0.0f;
        #pragma unroll
        for (int ch = 0; ch < 2; ch++) {
            const int cl = c0g + ch * 16;
            float d[16], nsi[16], nsj[16];
            #pragma unroll
            for (int c = 0; c < 16; c++) d[c] = Cs0[r * CSTRIDE + cl + c] + __ldg(b_edge + cl + c);
            const float4* pi4 = (const float4*)(ns + (size_t)ii * H + cl);
            const float4* pj4 = (const float4*)(ns + (size_t)jj * H + cl);
            #pragma unroll
            for (int q = 0; q < 4; q++) {
                float4 a = __ldg(pi4 + q);
                nsi[4*q] = a.x; nsi[4*q+1] = a.y; nsi[4*q+2] = a.z; nsi[4*q+3] = a.w;
                float4 b = __ldg(pj4 + q);
                nsj[4*q] = b.x; nsj[4*q+1] = b.y; nsj[4*q+2] = b.z; nsj[4*q+3] = b.w;
            }
            float s = 0.f;
            #pragma unroll
            for (int c = 0; c < 16; c++) {
                float ef = silu_f(d[c]);
                d[c] = ef;
                s += silu_f(nsi[c] + nsj[c] + ef) * __ldg(alpha + cl + c);
            }
            float attn = s * cut;
            #pragma unroll
            for (int c = 0; c < 16; c++)
                Cs0[r * CSTRIDE + cl + c] = nsj[c] * d[c] * attn;
        }
    }
    __syncthreads();

    // Edge-final epilogue in FRAGMENT layout (accF + efeat still in A)
    {
        const int gid = lane >> 2, tig = lane & 3;
        #pragma unroll
        for (int mt = 0; mt < 2; mt++) {
            #pragma unroll
            for (int rg = 0; rg < 2; rg++) {
                int r = warp_m * 32 + mt * 16 + rg * 8 + gid;
                int ii = sOwn[r], jj = sEj[r], eorig = sEid[r];
                float v0 = sEv[r * 3 + 0], v1 = sEv[r * 3 + 1], v2 = sEv[r * 3 + 2];
                float vvq = v0 * v0 + v1 * v1 + v2 * v2;
                const float* arow = nv_cross + (size_t)ii * 384;
                const float* brow = nv_cross + (size_t)jj * 384;
                float* dst = out_edge + (size_t)eorig * H;
                #pragma unroll
                for (int nt = 0; nt < 4; nt++) {
                    int c = warp_n * 32 + nt * 8 + tig * 2;
                    float d0 = accF[mt][nt][rg * 2 + 0] + __ldg(b_f + c);
                    float d1 = accF[mt][nt][rg * 2 + 1] + __ldg(b_f + c + 1);
                    uint32_t h2 = *(uint32_t*)(smem + (r * ASTRIDE + c) * 2);
                    uint32_t l2 = *(uint32_t*)(smem + A_LO + (r * ASTRIDE + c) * 2);
                    float2 hf = __bfloat1622float2(*(__nv_bfloat162*)&h2);
                    float2 lf = __bfloat1622float2(*(__nv_bfloat162*)&l2);
                    float2 a0 = __ldg((const float2*)(arow + c));
                    float2 a1 = __ldg((const float2*)(arow + 128 + c));
                    float2 a2 = __ldg((const float2*)(arow + 256 + c));
                    float2 b0 = __ldg((const float2*)(brow + c));
                    float2 b1 = __ldg((const float2*)(brow + 128 + c));
                    float2 b2 = __ldg((const float2*)(brow + 256 + c));
                    float ab0 = a0.x * b0.x + a1.x * b1.x + a2.x * b2.x;
                    float av0 = a0.x * v0 + a1.x * v1 + a2.x * v2;
                    float bv0 = b0.x * v0 + b1.x * v1 + b2.x * v2;
                    float ab1 = a0.y * b0.y + a1.y * b1.y + a2.y * b2.y;
                    float av1 = a0.y * v0 + a1.y * v1 + a2.y * v2;
                    float bv1 = b0.y * v0 + b1.y * v1 + b2.y * v2;
                    float2 o;
                    o.x = (hf.x + lf.x) + silu_f(d0) * (ab0 * vvq - av0 * bv0);
                    o.y = (hf.y + lf.y) + silu_f(d1) * (ab1 * vvq - av1 * bv1);
                    __stcs((float2*)(dst + c), o);
                }
            }
        }
    }

    // Phase D: scalar agg walk (col-pair x quarter)
    {
        int qp = tid & 63, hf = tid >> 6;
        int rbeg = hf * 16, rend = rbeg + 16;
        int c0 = qp * 2;
        float a0 = 0.f, a1 = 0.f;
        int prev = sOwn[rbeg];
        #pragma unroll 4
        for (int r2 = rbeg; r2 < rend; r2++) {
            int o = sOwn[r2];
            float2 v = *(float2*)&Cs0[r2 * CSTRIDE + c0];
            if (o != prev) {
                atomicAdd(&ns1[(size_t)prev * H + c0], a0);
                atomicAdd(&ns1[(size_t)prev * H + c0 + 1], a1);
                a0 = a1 = 0.f; prev = o;
            }
            a0 += v.x; a1 += v.y;
        }
        atomicAdd(&ns1[(size_t)prev * H + c0], a0);
        atomicAdd(&ns1[(size_t)prev * H + c0 + 1], a1);
    }
    __syncthreads();   // all A reads (edge-final epi) + Cs0 reads done

    // Phase E: re-split msg (Cs0) into bf16 A region
    {
        int r = tid >> 2, k0 = (tid & 3) * 32;
        #pragma unroll
        for (int q = 0; q < 8; q++) {
            int k = k0 + q * 4;
            float4 a = make_float4(Cs0[r * CSTRIDE + k], Cs0[r * CSTRIDE + k + 1],
                                   Cs0[r * CSTRIDE + k + 2], Cs0[r * CSTRIDE + k + 3]);
            a_split_store(smem, r, k0 + q * 4, a);
        }
    }
    __syncthreads();

    // Fused mainloop 2: s1 (Wp1a -> accE), s2 (Wp1b -> accF)
    zero_acc(accE);
    zero_acc(accF);
    mma_mainloop_dual(accE, accF, aoff, sb, Bp1a, Bp1b, warp_n, lane);
    stage_c(Cs0, accE, lane, warp_m, warp_n);   // Cs0 not read since Phase E
    __syncthreads();                             // all A LDSM reads done
    stage_c(As, accF, lane, warp_m, warp_n);     // s2 over dead A region
    __syncthreads();

    // Phase I: vmsg walk (s1 in Cs0, s2 in As)
    {
        const int qp = tid & 63, hf = tid >> 6;
        const int rbeg = hf * 16, rend = rbeg + 16;
        const int c0 = qp * 2;
        float2 b1 = __ldg((const float2*)(b_p1 + c0));
        float2 b2 = __ldg((const float2*)(b_p1 + 128 + c0));
        float a00 = 0.f, a01 = 0.f, a10 = 0.f, a11 = 0.f, a20 = 0.f, a21 = 0.f;
        int prev = sOwn[rbeg];
        #pragma unroll 4
        for (int r2 = rbeg; r2 < rend; r2++) {
            int o = sOwn[r2];
            int j = sEj[r2];
            float2 s1v = *(float2*)&Cs0[r2 * CSTRIDE + c0];
            float2 s2v = *(float2*)&As[r2 * CSTRIDE + c0];
            float s1a = silu_f(s1v.x + b1.x), s1b = silu_f(s1v.y + b1.y);
            float s2a = silu_f(s2v.x + b2.x), s2b = silu_f(s2v.y + b2.y);
            const float* nv = nvec + (size_t)j * 384 + c0;
            float2 n0 = __ldg((const float2*)nv);
            float2 n1 = __ldg((const float2*)(nv + 128));
            float2 n2 = __ldg((const float2*)(nv + 256));
            float e0 = sEv[r2 * 3 + 0], e1 = sEv[r2 * 3 + 1], e2 = sEv[r2 * 3 + 2];
            if (o != prev) {
                atomicAdd(&nvec1[(size_t)prev * 384 + c0], a00);
                atomicAdd(&nvec1[(size_t)prev * 384 + c0 + 1], a01);
                atomicAdd(&nvec1[(size_t)prev * 384 + 128 + c0], a10);
                atomicAdd(&nvec1[(size_t)prev * 384 + 128 + c0 + 1], a11);
                atomicAdd(&nvec1[(size_t)prev * 384 + 256 + c0], a20);
                atomicAdd(&nvec1[(size_t)prev * 384 + 256 + c0 + 1], a21);
                a00 = a01 = a10 = a11 = a20 = a21 = 0.f; prev = o;
            }
            a00 = fmaf(n0.x, s1a, fmaf(s2a, e0, a00));
            a01 = fmaf(n0.y, s1b, fmaf(s2b, e0, a01));
            a10 = fmaf(n1.x, s1a, fmaf(s2a, e1, a10));
            a11 = fmaf(n1.y, s1b, fmaf(s2b, e1, a11));
            a20 = fmaf(n2.x, s1a, fmaf(s2a, e2, a20));
            a21 = fmaf(n2.y, s1b, fmaf(s2b, e2, a21));
        }
        atomicAdd(&nvec1[(size_t)prev * 384 + c0], a00);
        atomicAdd(&nvec1[(size_t)prev * 384 + c0 + 1], a01);
        atomicAdd(&nvec1[(size_t)prev * 384 + 128 + c0], a10);
        atomicAdd(&nvec1[(size_t)prev * 384 + 128 + c0 + 1], a11);
        atomicAdd(&nvec1[(size_t)prev * 384 + 256 + c0], a20);
        atomicAdd(&nvec1[(size_t)prev * 384 + 256 + c0 + 1], a21);
    }
}

// ========================= node final =========================
__global__ void node_final(float* __restrict__ out_scal,
                           float* __restrict__ out_vec) {
    int n = blockIdx.x;
    int h = threadIdx.x;
    float v1d[3], v2d[3];
    #pragma unroll
    for (int d = 0; d < 3; d++) {
        v1d[d] = g_wv[((size_t)n * 3 + d) * 256 + h];
        v2d[d] = g_wv[((size_t)n * 3 + d) * 256 + 128 + h];
    }
    float tri = v1d[0] * v2d[0] + v1d[1] * v2d[1] + v1d[2] * v2d[2];
    float sq  = v2d[0] * v2d[0] + v2d[1] * v2d[1] + v2d[2] * v2d[2];
    float nrm = sqrtf(sq + 1e-8f);
    float qua = nrm * nrm * nrm;
    float p1 = g_p[(size_t)n * 384 + h];
    float p2 = g_p[(size_t)n * 384 + 128 + h];
    float p3 = g_p[(size_t)n * 384 + 256 + h];
    out_scal[(size_t)n * H + h] = g_ns1[(size_t)n * H + h] + (qua + tri) * p1 + p2;
    #pragma unroll
    for (int d = 0; d < 3; d++) {
        out_vec[((size_t)n * 3 + d) * H + h] =
            g_nvec1[((size_t)n * 3 + d) * H + h] + v1d[d] * p3;
    }
}

// ========================= launch =========================
extern "C" void kernel_launch(void* const* d_in, const int* in_sizes, int n_in,
                              void* d_out, int out_size) {
    const float* node_scalar = (const float*)d_in[0];
    const float* node_vector = (const float*)d_in[1];
    const int*   edge_index  = (const int*)  d_in[2];
    const float* dist        = (const float*)d_in[3];
    const float* edge_feats  = (const float*)d_in[4];
    const float* edge_vector = (const float*)d_in[5];
    const float* ln_gamma    = (const float*)d_in[6];
    const float* ln_beta     = (const float*)d_in[7];
    const float* alpha       = (const float*)d_in[8];
    const float* W_cross     = (const float*)d_in[9];
    const float* W_node      = (const float*)d_in[10];
    const float* b_node      = (const float*)d_in[11];
    const float* W_edge      = (const float*)d_in[12];
    const float* b_edge      = (const float*)d_in[13];
    const float* W_p1        = (const float*)d_in[14];
    const float* b_p1        = (const float*)d_in[15];
    const float* W_p2        = (const float*)d_in[16];
    const float* b_p2        = (const float*)d_in[17];
    const float* W_vec       = (const float*)d_in[18];
    const float* W_f         = (const float*)d_in[19];
    const float* b_f         = (const float*)d_in[20];

    float* out = (float*)d_out;
    float* out_scal = out;
    float* out_vec  = out + (size_t)N_NODES * H;
    float* out_edge = out + (size_t)N_NODES * H * 4;

    float* p_ns;    cudaGetSymbolAddress((void**)&p_ns, g_ns);
    float* p_nv;    cudaGetSymbolAddress((void**)&p_nv, g_nv);
    float* p_ns1;   cudaGetSymbolAddress((void**)&p_ns1, g_ns1);
    float* p_nvec1; cudaGetSymbolAddress((void**)&p_nvec1, g_nvec1);
    float* p_wv;    cudaGetSymbolAddress((void**)&p_wv, g_wv);
    float* p_p;     cudaGetSymbolAddress((void**)&p_p, g_p);
    __nv_bfloat16* wp; cudaGetSymbolAddress((void**)&wp, g_wpack);
    int* p_eids;  cudaGetSymbolAddress((void**)&p_eids, g_eids);
    int* p_own;   cudaGetSymbolAddress((void**)&p_own, g_own);
    int* p_ej;    cudaGetSymbolAddress((void**)&p_ej, g_ej);
    float* p_distc; cudaGetSymbolAddress((void**)&p_distc, g_distc);
    float* p_evc;   cudaGetSymbolAddress((void**)&p_evc, g_evc);

    cudaFuncSetAttribute(scatter_gemmA, cudaFuncAttributeMaxDynamicSharedMemorySize, SM_GEMM);
    cudaFuncSetAttribute(gemmB, cudaFuncAttributeMaxDynamicSharedMemorySize, SM_GEMM);
    cudaFuncSetAttribute(mega_msg, cudaFuncAttributeMaxDynamicSharedMemorySize, SM_MEGA);

    // 1: weight pack + distributed edge histogram (22 blocks)
    pack_hist<<<22, 1024>>>(W_node, W_edge, W_p1, W_cross, W_f, W_vec, W_p2, edge_index);
    // 2: scan (1 block, self-cleans g_deg)
    csr_scan<<<1, 1024>>>();
    // 3: csr_scatter + gemmA (merged)
    scatter_gemmA<<<SCAT_BLKS + GB_3N + GB_N, 256, SM_GEMM>>>(
        edge_index, dist, edge_vector,
        node_scalar, node_vector, wp + 0 * 32768, wp + 4 * 32768,
        b_node, ln_gamma, ln_beta, p_ns, p_nv, p_ns1, p_nvec1);
    // 4: message path + edge update (dual-acc fused)
    mega_msg<<<GB_E, 256, SM_MEGA>>>(edge_feats, wp + 1 * 32768, wp + 2 * 32768, wp + 5 * 32768,
                                     b_edge, b_p1, b_f, p_eids, p_own, p_ej, p_distc,
                                     alpha, p_evc, p_ns, node_vector, p_nv,
                                     p_ns1, p_nvec1, out_edge);
    // 5: wv + p (combined)
    gemmB<<<GB_3N * 2 + GB_N * 3, 256, SM_GEMM>>>(p_nvec1, p_ns1,
                                                  wp + 6 * 32768, wp + 8 * 32768,
                                                  b_p2, p_wv, p_p);
    // 6
    node_final<<<N_NODES, 128>>>(out_scal, out_vec);
}

// round 16
// speedup vs baseline: 1.0739x; 1.0739x over previous
#include <cuda_runtime.h>
#include <cuda_bf16.h>
#include <math.h>
#include <stdint.h>

#define N_NODES 20000
#define N_EDGES 320000
#define H 128
#define CUTOFF_R 5.0f
#define PI_F 3.14159265358979323846f

// ========================= scratch (device globals) =========================
__device__ __align__(16) float g_ns[N_NODES * H];
__device__ __align__(16) float g_nv[N_NODES * 3 * H];
__device__ __align__(16) float g_ns1[N_NODES * H];
__device__ __align__(16) float g_nvec1[N_NODES * 3 * H];
__device__ __align__(16) float g_wv[N_NODES * 3 * 2 * H];
__device__ __align__(16) float g_p[N_NODES * 3 * H];
__device__ __align__(16) __nv_bfloat16 g_wpack[11 * 32768];

__device__ int g_deg[N_NODES];      // zero-init; scan() re-zeros after use
__device__ int g_off[N_NODES + 1];
__device__ int g_cur[N_NODES];
__device__ int g_eids[N_EDGES];
__device__ int g_own[N_EDGES];
__device__ int g_ej[N_EDGES];
__device__ float g_distc[N_EDGES];
__device__ float g_evc[N_EDGES * 3];

// ========================= helpers =========================
__device__ __forceinline__ uint32_t smem_u32(const void* p) {
    uint32_t a;
    asm("{ .reg .u64 t; cvta.to.shared.u64 t, %1; cvt.u32.u64 %0, t; }" : "=r"(a) : "l"(p));
    return a;
}
__device__ __forceinline__ float silu_f(float x) { return x / (1.0f + __expf(-x)); }

#define LDSM4(r, addr) \
    asm volatile("ldmatrix.sync.aligned.m8n8.x4.shared.b16 {%0,%1,%2,%3}, [%4];" \
        : "=r"((r)[0]), "=r"((r)[1]), "=r"((r)[2]), "=r"((r)[3]) : "r"(addr))

#define MMA16816(c, a, b) \
    asm volatile("mma.sync.aligned.m16n8k16.row.col.f32.bf16.bf16.f32 " \
        "{%0,%1,%2,%3}, {%4,%5,%6,%7}, {%8,%9}, {%0,%1,%2,%3};" \
        : "+f"((c)[0]), "+f"((c)[1]), "+f"((c)[2]), "+f"((c)[3]) \
        : "r"((a)[0]), "r"((a)[1]), "r"((a)[2]), "r"((a)[3]), "r"((b)[0]), "r"((b)[1]))

// ========================= pack + distributed histogram ======================
__global__ void pack_hist(const float* __restrict__ Wn, const float* __restrict__ We,
                          const float* __restrict__ Wp1, const float* __restrict__ Wc,
                          const float* __restrict__ Wf, const float* __restrict__ Wv,
                          const float* __restrict__ Wp2,
                          const int* __restrict__ ei) {
    const int tid = threadIdx.x;
    int b = blockIdx.x;
    {
        const int per_blk = (N_EDGES + 21) / 22;
        int beg = b * per_blk;
        int end = min(beg + per_blk, N_EDGES);
        for (int e = beg + tid; e < end; e += 1024)
            atomicAdd(&g_deg[__ldg(ei + e)], 1);
    }
    int tile = b >> 1, half = b & 1;
    const float* W; int ncol, t;
    switch (tile) {
        case 0: W = Wn;  ncol = 128; t = 0; break;
        case 1: W = We;  ncol = 128; t = 0; break;
        case 2: case 3: W = Wp1; ncol = 256; t = tile - 2; break;
        case 4: W = Wc;  ncol = 128; t = 0; break;
        case 5: W = Wf;  ncol = 128; t = 0; break;
        case 6: case 7: W = Wv;  ncol = 256; t = tile - 6; break;
        default: W = Wp2; ncol = 384; t = tile - 8; break;
    }
    uint32_t* dst = (uint32_t*)(g_wpack + (size_t)tile * 32768);
    #pragma unroll
    for (int q = 0; q < 4; q++) {
        int e = half * 4096 + tid * 4 + q;
        int r = e & 7, lane = (e >> 3) & 31, ks = (e >> 8) & 7, wn = e >> 11;
        int n = wn * 32 + (r >> 1) * 8 + (lane >> 2);
        int k = ks * 16 + (r & 1) * 8 + (lane & 3) * 2;
        float v0 = W[(size_t)k * ncol + t * 128 + n];
        float v1 = W[(size_t)(k + 1) * ncol + t * 128 + n];
        __nv_bfloat16 h0 = __float2bfloat16(v0);
        __nv_bfloat16 h1 = __float2bfloat16(v1);
        __nv_bfloat16 l0 = __float2bfloat16(v0 - __bfloat162float(h0));
        __nv_bfloat16 l1 = __float2bfloat16(v1 - __bfloat162float(h1));
        uint32_t hp = (uint32_t)*(uint16_t*)&h0 | ((uint32_t)*(uint16_t*)&h1 << 16);
        uint32_t lp = (uint32_t)*(uint16_t*)&l0 | ((uint32_t)*(uint16_t*)&l1 << 16);
        dst[e] = hp;
        dst[8192 + e] = lp;
    }
}

// single-block exclusive scan (self-cleans g_deg)
__global__ void csr_scan() {
    const int tid = threadIdx.x;
    const int lane = tid & 31, w = tid >> 5;
    __shared__ int wsum[32];
    __shared__ int carry;
    if (tid == 0) carry = 0;
    __syncthreads();
    for (int base = 0; base < N_NODES; base += 1024) {
        int idx = base + tid;
        int v = (idx < N_NODES) ? g_deg[idx] : 0;
        if (idx < N_NODES) g_deg[idx] = 0;
        int s = v;
        #pragma unroll
        for (int o = 1; o < 32; o <<= 1) {
            int t = __shfl_up_sync(0xffffffffu, s, o);
            if (lane >= o) s += t;
        }
        if (lane == 31) wsum[w] = s;
        __syncthreads();
        if (w == 0) {
            int x = wsum[lane];
            #pragma unroll
            for (int o = 1; o < 32; o <<= 1) {
                int t = __shfl_up_sync(0xffffffffu, x, o);
                if (lane >= o) x += t;
            }
            wsum[lane] = x;
        }
        __syncthreads();
        int blockoff = (w > 0) ? wsum[w - 1] : 0;
        int c = carry;
        if (idx < N_NODES) {
            int excl = c + blockoff + s - v;
            g_off[idx] = excl;
            g_cur[idx] = excl;
        }
        int tot = wsum[31];
        __syncthreads();
        if (tid == 0) carry = c + tot;
        __syncthreads();
    }
    if (tid == 0) g_off[N_NODES] = carry;
}

// ========================= shared GEMM plumbing (64-row tiles) ==============
#define ASTRIDE 136
#define CSTRIDE 132
#define A_LO    17408
#define SM_GEMM 34816
#define SM_MEGA 70144

__device__ __forceinline__ void a_split_store(char* smem, int r, int k0, float4 a) {
    __nv_bfloat162 h01 = __float22bfloat162_rn(make_float2(a.x, a.y));
    __nv_bfloat162 h23 = __float22bfloat162_rn(make_float2(a.z, a.w));
    float2 f01 = __bfloat1622float2(h01);
    float2 f23 = __bfloat1622float2(h23);
    __nv_bfloat162 l01 = __float22bfloat162_rn(make_float2(a.x - f01.x, a.y - f01.y));
    __nv_bfloat162 l23 = __float22bfloat162_rn(make_float2(a.z - f23.x, a.w - f23.y));
    uint2 hv, lv;
    hv.x = *(uint32_t*)&h01; hv.y = *(uint32_t*)&h23;
    lv.x = *(uint32_t*)&l01; lv.y = *(uint32_t*)&l23;
    *(uint2*)(smem + (r * ASTRIDE + k0) * 2) = hv;
    *(uint2*)(smem + A_LO + (r * ASTRIDE + k0) * 2) = lv;
}

__device__ __forceinline__ void mma_setup(uint32_t aoff[2], int lane, int warp_m) {
    const int rin = lane & 7, sel = lane >> 3;
    #pragma unroll
    for (int mt = 0; mt < 2; mt++) {
        int row = warp_m * 32 + mt * 16 + (sel & 1) * 8 + rin;
        int col = (sel >> 1) * 8;
        aoff[mt] = (uint32_t)((row * ASTRIDE + col) * 2);
    }
}

__device__ __forceinline__ void zero_acc(float acc[2][4][4]) {
    #pragma unroll
    for (int mt = 0; mt < 2; mt++)
        #pragma unroll
        for (int nt = 0; nt < 4; nt++)
            #pragma unroll
            for (int u = 0; u < 4; u++) acc[mt][nt][u] = 0.f;
}

__device__ __forceinline__ void mma_mainloop(float acc[2][4][4], const uint32_t aoff[2],
                                             uint32_t sb, const uint4* __restrict__ Bp,
                                             int warp_n, int lane) {
    const uint32_t aHi = sb, aLo = sb + A_LO;
    #pragma unroll
    for (int ks = 0; ks < 8; ks++) {
        uint32_t kb = ks * 32;
        uint32_t ah[2][4], al[2][4];
        int idx = ((warp_n * 8 + ks) * 32 + lane) * 2;
        uint4 u0 = __ldg(Bp + idx);
        uint4 u1 = __ldg(Bp + idx + 1);
        uint4 l0 = __ldg(Bp + idx + 2048);
        uint4 l1 = __ldg(Bp + idx + 2049);
        LDSM4(ah[0], aHi + aoff[0] + kb);
        LDSM4(ah[1], aHi + aoff[1] + kb);
        LDSM4(al[0], aLo + aoff[0] + kb);
        LDSM4(al[1], aLo + aoff[1] + kb);
        uint32_t bh[4][2], bl[4][2];
        bh[0][0] = u0.x; bh[0][1] = u0.y; bh[1][0] = u0.z; bh[1][1] = u0.w;
        bh[2][0] = u1.x; bh[2][1] = u1.y; bh[3][0] = u1.z; bh[3][1] = u1.w;
        bl[0][0] = l0.x; bl[0][1] = l0.y; bl[1][0] = l0.z; bl[1][1] = l0.w;
        bl[2][0] = l1.x; bl[2][1] = l1.y; bl[3][0] = l1.z; bl[3][1] = l1.w;
        #pragma unroll
        for (int mt = 0; mt < 2; mt++)
            #pragma unroll
            for (int nt = 0; nt < 4; nt++) {
                MMA16816(acc[mt][nt], ah[mt], bh[nt]);
                MMA16816(acc[mt][nt], ah[mt], bl[nt]);
                MMA16816(acc[mt][nt], al[mt], bh[nt]);
            }
    }
}

__device__ __forceinline__ void stage_c(float* Cs, const float acc[2][4][4],
                                        int lane, int warp_m, int warp_n) {
    int gid = lane >> 2, tig = lane & 3;
    #pragma unroll
    for (int mt = 0; mt < 2; mt++) {
        int r = warp_m * 32 + mt * 16 + gid;
        #pragma unroll
        for (int nt = 0; nt < 4; nt++) {
            int cc = warp_n * 32 + nt * 8 + tig * 2;
            *(float2*)&Cs[r * CSTRIDE + cc] = make_float2(acc[mt][nt][0], acc[mt][nt][1]);
            *(float2*)&Cs[(r + 8) * CSTRIDE + cc] = make_float2(acc[mt][nt][2], acc[mt][nt][3]);
        }
    }
}

// ========================= GEMM body (modes 0,1,2) ===========================
__device__ __forceinline__ void gemm_body(
        char* smem,
        const float* __restrict__ A, int M,
        const __nv_bfloat16* __restrict__ Bpack,
        const float* __restrict__ bias,
        float* __restrict__ C, int ldc, int mode,
        const float* __restrict__ gamma,
        const float* __restrict__ beta,
        float* __restrict__ aux,
        int row0, int ncoff) {
    const int tid = threadIdx.x;
    const int lane = tid & 31, wid = tid >> 5;
    const int warp_m = wid >> 2, warp_n = wid & 3;
    const uint4* Bp = (const uint4*)Bpack;
    const uint32_t sb = smem_u32(smem);

    {
        int r = tid >> 2, k0 = (tid & 3) * 32;
        int arow = row0 + r;
        bool vr = arow < M;
        const float4* src = (const float4*)(A + (size_t)arow * 128 + k0);
        float4 av[8];
        #pragma unroll
        for (int q = 0; q < 8; q++)
            av[q] = vr ? __ldg(src + q) : make_float4(0.f, 0.f, 0.f, 0.f);

        if (mode >= 1 && vr) {
            float4* dstaux = (float4*)(aux + (size_t)arow * 128 + k0);
            #pragma unroll
            for (int q = 0; q < 8; q++) dstaux[q] = av[q];
        }
        if (mode == 1) {
            float s = 0.f, s2 = 0.f;
            #pragma unroll
            for (int q = 0; q < 8; q++) {
                s  += av[q].x + av[q].y + av[q].z + av[q].w;
                s2 += av[q].x*av[q].x + av[q].y*av[q].y + av[q].z*av[q].z + av[q].w*av[q].w;
            }
            s  += __shfl_xor_sync(0xffffffffu, s, 1);
            s  += __shfl_xor_sync(0xffffffffu, s, 2);
            s2 += __shfl_xor_sync(0xffffffffu, s2, 1);
            s2 += __shfl_xor_sync(0xffffffffu, s2, 2);
            float mu = s * (1.0f / H);
            float var = s2 * (1.0f / H) - mu * mu;
            float inv = rsqrtf(var + 1e-5f);
            #pragma unroll
            for (int q = 0; q < 8; q++) {
                int k = k0 + q * 4;
                float4 gm = __ldg((const float4*)(gamma + k));
                float4 bt = __ldg((const float4*)(beta + k));
                av[q].x = (av[q].x - mu) * inv * gm.x + bt.x;
                av[q].y = (av[q].y - mu) * inv * gm.y + bt.y;
                av[q].z = (av[q].z - mu) * inv * gm.z + bt.z;
                av[q].w = (av[q].w - mu) * inv * gm.w + bt.w;
            }
        }
        #pragma unroll
        for (int q = 0; q < 8; q++)
            a_split_store(smem, r, k0 + q * 4, av[q]);
    }
    __syncthreads();

    float acc[2][4][4];
    zero_acc(acc);
    uint32_t aoff[2];
    mma_setup(aoff, lane, warp_m);
    mma_mainloop(acc, aoff, sb, Bp, warp_n, lane);
    __syncthreads();

    float* Cs = (float*)smem;
    stage_c(Cs, acc, lane, warp_m, warp_n);
    __syncthreads();

    const int r = tid >> 2;
    const int c0g = (tid & 3) * 32;
    const int grow = row0 + r;
    if (grow >= M) return;
    float* dst = C + (size_t)grow * ldc + ncoff + c0g;

    #pragma unroll
    for (int ch = 0; ch < 2; ch++) {
        const int cl = c0g + ch * 16;
        float d[16];
        #pragma unroll
        for (int c = 0; c < 16; c++) d[c] = Cs[r * CSTRIDE + cl + c];
        if (bias) {
            #pragma unroll
            for (int c = 0; c < 16; c++) d[c] += __ldg(bias + cl + c);
        }
        #pragma unroll
        for (int q = 0; q < 4; q++)
            *(float4*)(dst + ch * 16 + 4 * q) =
                make_float4(d[4*q], d[4*q+1], d[4*q+2], d[4*q+3]);
    }
}

#define GB_N  ((N_NODES + 63) / 64)       // 313
#define GB_3N ((3 * N_NODES + 63) / 64)   // 938
#define GB_E  (N_EDGES / 64)              // 5000
#define SCAT_BLKS ((N_EDGES + 255) / 256) // 1250

// ===== merged launch: csr_scatter blocks + gemmA blocks ======================
__global__ __launch_bounds__(256, 4)
void scatter_gemmA(const int* __restrict__ ei,
                   const float* __restrict__ dist,
                   const float* __restrict__ ev,
                   const float* __restrict__ node_scalar,
                   const float* __restrict__ node_vector,
                   const __nv_bfloat16* __restrict__ wpN,
                   const __nv_bfloat16* __restrict__ wpC,
                   const float* __restrict__ b_node,
                   const float* __restrict__ gamma,
                   const float* __restrict__ beta,
                   float* __restrict__ ns, float* __restrict__ nv,
                   float* __restrict__ ns1, float* __restrict__ nvec1) {
    extern __shared__ char smem[];
    int bx = blockIdx.x;
    if (bx < SCAT_BLKS) {
        int e = bx * 256 + threadIdx.x;
        if (e < N_EDGES) {
            int i = ei[e];
            int j = ei[N_EDGES + e];
            int pos = atomicAdd(&g_cur[i], 1);
            g_eids[pos] = e;
            g_own[pos] = i;
            g_ej[pos] = j;
            g_distc[pos] = dist[e];
            g_evc[pos * 3 + 0] = ev[e * 3 + 0];
            g_evc[pos * 3 + 1] = ev[e * 3 + 1];
            g_evc[pos * 3 + 2] = ev[e * 3 + 2];
        }
        return;
    }
    bx -= SCAT_BLKS;
    if (bx < GB_3N) {
        gemm_body(smem, node_vector, 3 * N_NODES, wpC, nullptr,
                  nv, 128, 2, nullptr, nullptr, nvec1, bx * 64, 0);
    } else {
        gemm_body(smem, node_scalar, N_NODES, wpN, b_node,
                  ns, 128, 1, gamma, beta, ns1, (bx - GB_3N) * 64, 0);
    }
}

// ===== combined launch B =====
__global__ __launch_bounds__(256, 4)
void gemmB(const float* __restrict__ nvec1,
           const float* __restrict__ ns1,
           const __nv_bfloat16* __restrict__ wpV,
           const __nv_bfloat16* __restrict__ wpP2,
           const float* __restrict__ b_p2,
           float* __restrict__ wv, float* __restrict__ p) {
    extern __shared__ char smem[];
    int bx = blockIdx.x;
    if (bx < GB_3N * 2) {
        int yt = bx & 1, rb = bx >> 1;
        gemm_body(smem, nvec1, 3 * N_NODES, wpV + (size_t)yt * 32768, nullptr,
                  wv, 256, 0, nullptr, nullptr, nullptr, rb * 64, yt * 128);
    } else {
        int idx = bx - GB_3N * 2;
        int yt = idx % 3, rb = idx / 3;
        gemm_body(smem, ns1, N_NODES, wpP2 + (size_t)yt * 32768, b_p2 + yt * 128,
                  p, 384, 0, nullptr, nullptr, nullptr, rb * 64, yt * 128);
    }
}

// ========================= MEGA message + edge-final (3 CTAs/SM) =============
__global__ __launch_bounds__(256, 3)
void mega_msg(const float* __restrict__ efeat,
              const __nv_bfloat16* __restrict__ Wedge,
              const __nv_bfloat16* __restrict__ Wp1,
              const __nv_bfloat16* __restrict__ Wf,
              const float* __restrict__ b_edge,
              const float* __restrict__ b_p1,
              const float* __restrict__ b_f,
              const int* __restrict__ eids,
              const int* __restrict__ own,
              const int* __restrict__ ejArr,
              const float* __restrict__ distc,
              const float* __restrict__ alpha,
              const float* __restrict__ evc,
              const float* __restrict__ ns,
              const float* __restrict__ nvec,
              const float* __restrict__ nv_cross,
              float* __restrict__ ns1,
              float* __restrict__ nvec1,
              float* __restrict__ out_edge) {
    extern __shared__ char smem[];
    const int tid = threadIdx.x;
    const int lane = tid & 31, wid = tid >> 5;
    const int warp_m = wid >> 2, warp_n = wid & 3;
    const int row0 = blockIdx.x * 64;
    const uint32_t sb = smem_u32(smem);
    const uint4* BpE = (const uint4*)Wedge;
    const uint4* Bp1a = (const uint4*)Wp1;
    const uint4* Bp1b = (const uint4*)(Wp1 + 32768);
    const uint4* BpF = (const uint4*)Wf;

    float* Cs0 = (float*)(smem + 34816);
    float* As  = (float*)smem;
    int* sOwn = (int*)(smem + 68608);
    int* sEj  = (int*)(smem + 68864);
    int* sEid = (int*)(smem + 69120);
    float* sEv = (float*)(smem + 69376);

    // Phase A: gathered edge_feats rows (streaming), split; meta
    {
        int r = tid >> 2, k0 = (tid & 3) * 32;
        int e = eids[row0 + r];
        const float4* src = (const float4*)(efeat + (size_t)e * 128 + k0);
        float4 av[8];
        #pragma unroll
        for (int q = 0; q < 8; q++) av[q] = __ldcs(src + q);
        #pragma unroll
        for (int q = 0; q < 8; q++) a_split_store(smem, r, k0 + q * 4, av[q]);
    }
    if (tid < 64) {
        sOwn[tid] = own[row0 + tid];
        sEj[tid]  = ejArr[row0 + tid];
        sEid[tid] = eids[row0 + tid];
        sEv[tid * 3 + 0] = evc[(row0 + tid) * 3 + 0];
        sEv[tid * 3 + 1] = evc[(row0 + tid) * 3 + 1];
        sEv[tid * 3 + 2] = evc[(row0 + tid) * 3 + 2];
    }
    __syncthreads();

    uint32_t aoff[2];
    mma_setup(aoff, lane, warp_m);

    // Phase B: ef GEMM (W_edge)
    float acc[2][4][4];
    zero_acc(acc);
    mma_mainloop(acc, aoff, sb, BpE, warp_n, lane);

    // Fragment-layout msg epilogue: compute msg directly from acc fragments,
    // single write into Cs0 (no stage/read round trip).
    {
        const int gid = lane >> 2, tig = lane & 3;
        #pragma unroll
        for (int mt = 0; mt < 2; mt++) {
            #pragma unroll
            for (int rg = 0; rg < 2; rg++) {
                int r = warp_m * 32 + mt * 16 + rg * 8 + gid;
                int ii = sOwn[r], jj = sEj[r];
                float dd = __ldg(distc + row0 + r);
                float cut = (dd < CUTOFF_R) ? 0.5f * (__cosf(PI_F * dd / CUTOFF_R) + 1.0f) : 0.0f;
                float efv[4][2], nsjv[4][2];
                float h0 = 0.f, h1 = 0.f;
                #pragma unroll
                for (int nt = 0; nt < 4; nt++) {
                    int c = warp_n * 32 + nt * 8 + tig * 2;
                    float2 be = __ldg((const float2*)(b_edge + c));
                    float2 al = __ldg((const float2*)(alpha + c));
                    float2 ni = __ldg((const float2*)(ns + (size_t)ii * H + c));
                    float2 nj = __ldg((const float2*)(ns + (size_t)jj * H + c));
                    float e0 = silu_f(acc[mt][nt][rg * 2 + 0] + be.x);
                    float e1 = silu_f(acc[mt][nt][rg * 2 + 1] + be.y);
                    efv[nt][0] = e0; efv[nt][1] = e1;
                    nsjv[nt][0] = nj.x; nsjv[nt][1] = nj.y;
                    float t0 = silu_f(ni.x + nj.x + e0) * al.x;
                    float t1 = silu_f(ni.y + nj.y + e1) * al.y;
                    if (nt < 2) h0 += t0 + t1; else h1 += t0 + t1;
                }
                // per-row head sums: reduce over the 4 tig lanes (quad)
                h0 += __shfl_xor_sync(0xffffffffu, h0, 1);
                h0 += __shfl_xor_sync(0xffffffffu, h0, 2);
                h1 += __shfl_xor_sync(0xffffffffu, h1, 1);
                h1 += __shfl_xor_sync(0xffffffffu, h1, 2);
                float attn0 = h0 * cut, attn1 = h1 * cut;
                #pragma unroll
                for (int nt = 0; nt < 4; nt++) {
                    int c = warp_n * 32 + nt * 8 + tig * 2;
                    float a = (nt < 2) ? attn0 : attn1;
                    float2 m;
                    m.x = nsjv[nt][0] * efv[nt][0] * a;
                    m.y = nsjv[nt][1] * efv[nt][1] * a;
                    *(float2*)&Cs0[r * CSTRIDE + c] = m;
                }
            }
        }
    }
    __syncthreads();

    // Phase Wf: GEMM (A still holds efeat) + edge-final epilogue in FRAGMENT layout
    zero_acc(acc);
    mma_mainloop(acc, aoff, sb, BpF, warp_n, lane);
    {
        const int gid = lane >> 2, tig = lane & 3;
        #pragma unroll
        for (int mt = 0; mt < 2; mt++) {
            #pragma unroll
            for (int rg = 0; rg < 2; rg++) {
                int r = warp_m * 32 + mt * 16 + rg * 8 + gid;
                int ii = sOwn[r], jj = sEj[r], eorig = sEid[r];
                float v0 = sEv[r * 3 + 0], v1 = sEv[r * 3 + 1], v2 = sEv[r * 3 + 2];
                float vvq = v0 * v0 + v1 * v1 + v2 * v2;
                const float* arow = nv_cross + (size_t)ii * 384;
                const float* brow = nv_cross + (size_t)jj * 384;
                float* dst = out_edge + (size_t)eorig * H;
                #pragma unroll
                for (int nt = 0; nt < 4; nt++) {
                    int c = warp_n * 32 + nt * 8 + tig * 2;
                    float d0 = acc[mt][nt][rg * 2 + 0] + __ldg(b_f + c);
                    float d1 = acc[mt][nt][rg * 2 + 1] + __ldg(b_f + c + 1);
                    uint32_t h2 = *(uint32_t*)(smem + (r * ASTRIDE + c) * 2);
                    uint32_t l2 = *(uint32_t*)(smem + A_LO + (r * ASTRIDE + c) * 2);
                    float2 hf = __bfloat1622float2(*(__nv_bfloat162*)&h2);
                    float2 lf = __bfloat1622float2(*(__nv_bfloat162*)&l2);
                    float2 a0 = __ldg((const float2*)(arow + c));
                    float2 a1 = __ldg((const float2*)(arow + 128 + c));
                    float2 a2 = __ldg((const float2*)(arow + 256 + c));
                    float2 b0 = __ldg((const float2*)(brow + c));
                    float2 b1 = __ldg((const float2*)(brow + 128 + c));
                    float2 b2 = __ldg((const float2*)(brow + 256 + c));
                    float ab0 = a0.x * b0.x + a1.x * b1.x + a2.x * b2.x;
                    float av0 = a0.x * v0 + a1.x * v1 + a2.x * v2;
                    float bv0 = b0.x * v0 + b1.x * v1 + b2.x * v2;
                    float ab1 = a0.y * b0.y + a1.y * b1.y + a2.y * b2.y;
                    float av1 = a0.y * v0 + a1.y * v1 + a2.y * v2;
                    float bv1 = b0.y * v0 + b1.y * v1 + b2.y * v2;
                    float2 o;
                    o.x = (hf.x + lf.x) + silu_f(d0) * (ab0 * vvq - av0 * bv0);
                    o.y = (hf.y + lf.y) + silu_f(d1) * (ab1 * vvq - av1 * bv1);
                    __stcs((float2*)(dst + c), o);
                }
            }
        }
    }

    // Phase D: scalar agg walk (col-pair x quarter; 16-iter chains)
    {
        int qp = tid & 63, hf = tid >> 6;
        int rbeg = hf * 16, rend = rbeg + 16;
        int c0 = qp * 2;
        float a0 = 0.f, a1 = 0.f;
        int prev = sOwn[rbeg];
        #pragma unroll 4
        for (int r2 = rbeg; r2 < rend; r2++) {
            int o = sOwn[r2];
            float2 v = *(float2*)&Cs0[r2 * CSTRIDE + c0];
            if (o != prev) {
                atomicAdd(&ns1[(size_t)prev * H + c0], a0);
                atomicAdd(&ns1[(size_t)prev * H + c0 + 1], a1);
                a0 = a1 = 0.f; prev = o;
            }
            a0 += v.x; a1 += v.y;
        }
        atomicAdd(&ns1[(size_t)prev * H + c0], a0);
        atomicAdd(&ns1[(size_t)prev * H + c0 + 1], a1);
    }
    __syncthreads();   // all A reads (Wf epi) + Cs0 reads done

    // Phase E: re-split msg (Cs0) into bf16 A region
    {
        int r = tid >> 2, k0 = (tid & 3) * 32;
        #pragma unroll
        for (int q = 0; q < 8; q++) {
            int k = k0 + q * 4;
            float4 a = make_float4(Cs0[r * CSTRIDE + k], Cs0[r * CSTRIDE + k + 1],
                                   Cs0[r * CSTRIDE + k + 2], Cs0[r * CSTRIDE + k + 3]);
            a_split_store(smem, r, k0 + q * 4, a);
        }
    }
    __syncthreads();

    // Phase F: Wp1 pass a -> stage s1 into Cs0 (msg dead)
    zero_acc(acc);
    mma_mainloop(acc, aoff, sb, Bp1a, warp_n, lane);
    stage_c(Cs0, acc, lane, warp_m, warp_n);

    // Phase G: Wp1 pass b
    zero_acc(acc);
    mma_mainloop(acc, aoff, sb, Bp1b, warp_n, lane);
    __syncthreads();   // all A reads done (pass b), s1 writes visible
    stage_c(As, acc, lane, warp_m, warp_n);   // s2 over dead A region
    __syncthreads();

    // Phase I: vmsg walk (s1 in Cs0, s2 in As)
    {
        const int qp = tid & 63, hf = tid >> 6;
        const int rbeg = hf * 16, rend = rbeg + 16;
        const int c0 = qp * 2;
        float2 b1 = __ldg((const float2*)(b_p1 + c0));
        float2 b2 = __ldg((const float2*)(b_p1 + 128 + c0));
        float a00 = 0.f, a01 = 0.f, a10 = 0.f, a11 = 0.f, a20 = 0.f, a21 = 0.f;
        int prev = sOwn[rbeg];
        #pragma unroll 4
        for (int r2 = rbeg; r2 < rend; r2++) {
            int o = sOwn[r2];
            int j = sEj[r2];
            float2 s1v = *(float2*)&Cs0[r2 * CSTRIDE + c0];
            float2 s2v = *(float2*)&As[r2 * CSTRIDE + c0];
            float s1a = silu_f(s1v.x + b1.x), s1b = silu_f(s1v.y + b1.y);
            float s2a = silu_f(s2v.x + b2.x), s2b = silu_f(s2v.y + b2.y);
            const float* nv = nvec + (size_t)j * 384 + c0;
            float2 n0 = __ldg((const float2*)nv);
            float2 n1 = __ldg((const float2*)(nv + 128));
            float2 n2 = __ldg((const float2*)(nv + 256));
            float e0 = sEv[r2 * 3 + 0], e1 = sEv[r2 * 3 + 1], e2 = sEv[r2 * 3 + 2];
            if (o != prev) {
                atomicAdd(&nvec1[(size_t)prev * 384 + c0], a00);
                atomicAdd(&nvec1[(size_t)prev * 384 + c0 + 1], a01);
                atomicAdd(&nvec1[(size_t)prev * 384 + 128 + c0], a10);
                atomicAdd(&nvec1[(size_t)prev * 384 + 128 + c0 + 1], a11);
                atomicAdd(&nvec1[(size_t)prev * 384 + 256 + c0], a20);
                atomicAdd(&nvec1[(size_t)prev * 384 + 256 + c0 + 1], a21);
                a00 = a01 = a10 = a11 = a20 = a21 = 0.f; prev = o;
            }
            a00 = fmaf(n0.x, s1a, fmaf(s2a, e0, a00));
            a01 = fmaf(n0.y, s1b, fmaf(s2b, e0, a01));
            a10 = fmaf(n1.x, s1a, fmaf(s2a, e1, a10));
            a11 = fmaf(n1.y, s1b, fmaf(s2b, e1, a11));
            a20 = fmaf(n2.x, s1a, fmaf(s2a, e2, a20));
            a21 = fmaf(n2.y, s1b, fmaf(s2b, e2, a21));
        }
        atomicAdd(&nvec1[(size_t)prev * 384 + c0], a00);
        atomicAdd(&nvec1[(size_t)prev * 384 + c0 + 1], a01);
        atomicAdd(&nvec1[(size_t)prev * 384 + 128 + c0], a10);
        atomicAdd(&nvec1[(size_t)prev * 384 + 128 + c0 + 1], a11);
        atomicAdd(&nvec1[(size_t)prev * 384 + 256 + c0], a20);
        atomicAdd(&nvec1[(size_t)prev * 384 + 256 + c0 + 1], a21);
    }
}

// ========================= node final =========================
__global__ void node_final(float* __restrict__ out_scal,
                           float* __restrict__ out_vec) {
    int n = blockIdx.x;
    int h = threadIdx.x;
    float v1d[3], v2d[3];
    #pragma unroll
    for (int d = 0; d < 3; d++) {
        v1d[d] = g_wv[((size_t)n * 3 + d) * 256 + h];
        v2d[d] = g_wv[((size_t)n * 3 + d) * 256 + 128 + h];
    }
    float tri = v1d[0] * v2d[0] + v1d[1] * v2d[1] + v1d[2] * v2d[2];
    float sq  = v2d[0] * v2d[0] + v2d[1] * v2d[1] + v2d[2] * v2d[2];
    float nrm = sqrtf(sq + 1e-8f);
    float qua = nrm * nrm * nrm;
    float p1 = g_p[(size_t)n * 384 + h];
    float p2 = g_p[(size_t)n * 384 + 128 + h];
    float p3 = g_p[(size_t)n * 384 + 256 + h];
    out_scal[(size_t)n * H + h] = g_ns1[(size_t)n * H + h] + (qua + tri) * p1 + p2;
    #pragma unroll
    for (int d = 0; d < 3; d++) {
        out_vec[((size_t)n * 3 + d) * H + h] =
            g_nvec1[((size_t)n * 3 + d) * H + h] + v1d[d] * p3;
    }
}

// ========================= launch =========================
extern "C" void kernel_launch(void* const* d_in, const int* in_sizes, int n_in,
                              void* d_out, int out_size) {
    const float* node_scalar = (const float*)d_in[0];
    const float* node_vector = (const float*)d_in[1];
    const int*   edge_index  = (const int*)  d_in[2];
    const float* dist        = (const float*)d_in[3];
    const float* edge_feats  = (const float*)d_in[4];
    const float* edge_vector = (const float*)d_in[5];
    const float* ln_gamma    = (const float*)d_in[6];
    const float* ln_beta     = (const float*)d_in[7];
    const float* alpha       = (const float*)d_in[8];
    const float* W_cross     = (const float*)d_in[9];
    const float* W_node      = (const float*)d_in[10];
    const float* b_node      = (const float*)d_in[11];
    const float* W_edge      = (const float*)d_in[12];
    const float* b_edge      = (const float*)d_in[13];
    const float* W_p1        = (const float*)d_in[14];
    const float* b_p1        = (const float*)d_in[15];
    const float* W_p2        = (const float*)d_in[16];
    const float* b_p2        = (const float*)d_in[17];
    const float* W_vec       = (const float*)d_in[18];
    const float* W_f         = (const float*)d_in[19];
    const float* b_f         = (const float*)d_in[20];

    float* out = (float*)d_out;
    float* out_scal = out;
    float* out_vec  = out + (size_t)N_NODES * H;
    float* out_edge = out + (size_t)N_NODES * H * 4;

    float* p_ns;    cudaGetSymbolAddress((void**)&p_ns, g_ns);
    float* p_nv;    cudaGetSymbolAddress((void**)&p_nv, g_nv);
    float* p_ns1;   cudaGetSymbolAddress((void**)&p_ns1, g_ns1);
    float* p_nvec1; cudaGetSymbolAddress((void**)&p_nvec1, g_nvec1);
    float* p_wv;    cudaGetSymbolAddress((void**)&p_wv, g_wv);
    float* p_p;     cudaGetSymbolAddress((void**)&p_p, g_p);
    __nv_bfloat16* wp; cudaGetSymbolAddress((void**)&wp, g_wpack);
    int* p_eids;  cudaGetSymbolAddress((void**)&p_eids, g_eids);
    int* p_own;   cudaGetSymbolAddress((void**)&p_own, g_own);
    int* p_ej;    cudaGetSymbolAddress((void**)&p_ej, g_ej);
    float* p_distc; cudaGetSymbolAddress((void**)&p_distc, g_distc);
    float* p_evc;   cudaGetSymbolAddress((void**)&p_evc, g_evc);

    cudaFuncSetAttribute(scatter_gemmA, cudaFuncAttributeMaxDynamicSharedMemorySize, SM_GEMM);
    cudaFuncSetAttribute(gemmB, cudaFuncAttributeMaxDynamicSharedMemorySize, SM_GEMM);
    cudaFuncSetAttribute(mega_msg, cudaFuncAttributeMaxDynamicSharedMemorySize, SM_MEGA);

    // 1: weight pack + distributed edge histogram (22 blocks)
    pack_hist<<<22, 1024>>>(W_node, W_edge, W_p1, W_cross, W_f, W_vec, W_p2, edge_index);
    // 2: scan (1 block, self-cleans g_deg)
    csr_scan<<<1, 1024>>>();
    // 3: csr_scatter + gemmA (merged)
    scatter_gemmA<<<SCAT_BLKS + GB_3N + GB_N, 256, SM_GEMM>>>(
        edge_index, dist, edge_vector,
        node_scalar, node_vector, wp + 0 * 32768, wp + 4 * 32768,
        b_node, ln_gamma, ln_beta, p_ns, p_nv, p_ns1, p_nvec1);
    // 4: message path + edge update (fragment-layout epilogues)
    mega_msg<<<GB_E, 256, SM_MEGA>>>(edge_feats, wp + 1 * 32768, wp + 2 * 32768, wp + 5 * 32768,
                                     b_edge, b_p1, b_f, p_eids, p_own, p_ej, p_distc,
                                     alpha, p_evc, p_ns, node_vector, p_nv,
                                     p_ns1, p_nvec1, out_edge);
    // 5: wv + p (combined)
    gemmB<<<GB_3N * 2 + GB_N * 3, 256, SM_GEMM>>>(p_nvec1, p_ns1,
                                                  wp + 6 * 32768, wp + 8 * 32768,
                                                  b_p2, p_wv, p_p);
    // 6
    node_final<<<N_NODES, 128>>>(out_scal, out_vec);
}

// round 17
// speedup vs baseline: 1.1156x; 1.0389x over previous
#include <cuda_runtime.h>
#include <cuda_bf16.h>
#include <math.h>
#include <stdint.h>

#define N_NODES 20000
#define N_EDGES 320000
#define H 128
#define CUTOFF_R 5.0f
#define PI_F 3.14159265358979323846f

// ========================= scratch (device globals) =========================
__device__ __align__(16) float g_ns[N_NODES * H];
__device__ __align__(16) float g_nv[N_NODES * 3 * H];
__device__ __align__(16) float g_ns1[N_NODES * H];
__device__ __align__(16) float g_nvec1[N_NODES * 3 * H];
__device__ __align__(16) float g_wv[N_NODES * 3 * 2 * H];
__device__ __align__(16) float g_p[N_NODES * 3 * H];
__device__ __align__(16) __nv_bfloat16 g_wpack[11 * 32768];

__device__ int g_deg[N_NODES];      // zero-init; scan() re-zeros after use
__device__ int g_off[N_NODES + 1];
__device__ int g_cur[N_NODES];
__device__ int g_eids[N_EDGES];
__device__ int g_own[N_EDGES];
__device__ int g_ej[N_EDGES];
__device__ float g_distc[N_EDGES];
__device__ float g_evc[N_EDGES * 3];

// ========================= helpers =========================
__device__ __forceinline__ uint32_t smem_u32(const void* p) {
    uint32_t a;
    asm("{ .reg .u64 t; cvta.to.shared.u64 t, %1; cvt.u32.u64 %0, t; }" : "=r"(a) : "l"(p));
    return a;
}
__device__ __forceinline__ float silu_f(float x) { return x / (1.0f + __expf(-x)); }

#define LDSM4(r, addr) \
    asm volatile("ldmatrix.sync.aligned.m8n8.x4.shared.b16 {%0,%1,%2,%3}, [%4];" \
        : "=r"((r)[0]), "=r"((r)[1]), "=r"((r)[2]), "=r"((r)[3]) : "r"(addr))

#define MMA16816(c, a, b) \
    asm volatile("mma.sync.aligned.m16n8k16.row.col.f32.bf16.bf16.f32 " \
        "{%0,%1,%2,%3}, {%4,%5,%6,%7}, {%8,%9}, {%0,%1,%2,%3};" \
        : "+f"((c)[0]), "+f"((c)[1]), "+f"((c)[2]), "+f"((c)[3]) \
        : "r"((a)[0]), "r"((a)[1]), "r"((a)[2]), "r"((a)[3]), "r"((b)[0]), "r"((b)[1]))

// ========================= pack + distributed histogram ======================
__global__ void pack_hist(const float* __restrict__ Wn, const float* __restrict__ We,
                          const float* __restrict__ Wp1, const float* __restrict__ Wc,
                          const float* __restrict__ Wf, const float* __restrict__ Wv,
                          const float* __restrict__ Wp2,
                          const int* __restrict__ ei) {
    const int tid = threadIdx.x;
    int b = blockIdx.x;
    {
        const int per_blk = (N_EDGES + 21) / 22;
        int beg = b * per_blk;
        int end = min(beg + per_blk, N_EDGES);
        for (int e = beg + tid; e < end; e += 1024)
            atomicAdd(&g_deg[__ldg(ei + e)], 1);
    }
    int tile = b >> 1, half = b & 1;
    const float* W; int ncol, t;
    switch (tile) {
        case 0: W = Wn;  ncol = 128; t = 0; break;
        case 1: W = We;  ncol = 128; t = 0; break;
        case 2: case 3: W = Wp1; ncol = 256; t = tile - 2; break;
        case 4: W = Wc;  ncol = 128; t = 0; break;
        case 5: W = Wf;  ncol = 128; t = 0; break;
        case 6: case 7: W = Wv;  ncol = 256; t = tile - 6; break;
        default: W = Wp2; ncol = 384; t = tile - 8; break;
    }
    uint32_t* dst = (uint32_t*)(g_wpack + (size_t)tile * 32768);
    #pragma unroll
    for (int q = 0; q < 4; q++) {
        int e = half * 4096 + tid * 4 + q;
        int r = e & 7, lane = (e >> 3) & 31, ks = (e >> 8) & 7, wn = e >> 11;
        int n = wn * 32 + (r >> 1) * 8 + (lane >> 2);
        int k = ks * 16 + (r & 1) * 8 + (lane & 3) * 2;
        float v0 = W[(size_t)k * ncol + t * 128 + n];
        float v1 = W[(size_t)(k + 1) * ncol + t * 128 + n];
        __nv_bfloat16 h0 = __float2bfloat16(v0);
        __nv_bfloat16 h1 = __float2bfloat16(v1);
        __nv_bfloat16 l0 = __float2bfloat16(v0 - __bfloat162float(h0));
        __nv_bfloat16 l1 = __float2bfloat16(v1 - __bfloat162float(h1));
        uint32_t hp = (uint32_t)*(uint16_t*)&h0 | ((uint32_t)*(uint16_t*)&h1 << 16);
        uint32_t lp = (uint32_t)*(uint16_t*)&l0 | ((uint32_t)*(uint16_t*)&l1 << 16);
        dst[e] = hp;
        dst[8192 + e] = lp;
    }
}

// single-block exclusive scan (self-cleans g_deg)
__global__ void csr_scan() {
    const int tid = threadIdx.x;
    const int lane = tid & 31, w = tid >> 5;
    __shared__ int wsum[32];
    __shared__ int carry;
    if (tid == 0) carry = 0;
    __syncthreads();
    for (int base = 0; base < N_NODES; base += 1024) {
        int idx = base + tid;
        int v = (idx < N_NODES) ? g_deg[idx] : 0;
        if (idx < N_NODES) g_deg[idx] = 0;
        int s = v;
        #pragma unroll
        for (int o = 1; o < 32; o <<= 1) {
            int t = __shfl_up_sync(0xffffffffu, s, o);
            if (lane >= o) s += t;
        }
        if (lane == 31) wsum[w] = s;
        __syncthreads();
        if (w == 0) {
            int x = wsum[lane];
            #pragma unroll
            for (int o = 1; o < 32; o <<= 1) {
                int t = __shfl_up_sync(0xffffffffu, x, o);
                if (lane >= o) x += t;
            }
            wsum[lane] = x;
        }
        __syncthreads();
        int blockoff = (w > 0) ? wsum[w - 1] : 0;
        int c = carry;
        if (idx < N_NODES) {
            int excl = c + blockoff + s - v;
            g_off[idx] = excl;
            g_cur[idx] = excl;
        }
        int tot = wsum[31];
        __syncthreads();
        if (tid == 0) carry = c + tot;
        __syncthreads();
    }
    if (tid == 0) g_off[N_NODES] = carry;
}

// ========================= shared GEMM plumbing (64-row tiles) ==============
#define ASTRIDE 136
#define CSTRIDE 132
#define A_LO    17408
#define SM_GEMM 34816
#define SM_MEGA 70144

__device__ __forceinline__ void a_split_store(char* smem, int r, int k0, float4 a) {
    __nv_bfloat162 h01 = __float22bfloat162_rn(make_float2(a.x, a.y));
    __nv_bfloat162 h23 = __float22bfloat162_rn(make_float2(a.z, a.w));
    float2 f01 = __bfloat1622float2(h01);
    float2 f23 = __bfloat1622float2(h23);
    __nv_bfloat162 l01 = __float22bfloat162_rn(make_float2(a.x - f01.x, a.y - f01.y));
    __nv_bfloat162 l23 = __float22bfloat162_rn(make_float2(a.z - f23.x, a.w - f23.y));
    uint2 hv, lv;
    hv.x = *(uint32_t*)&h01; hv.y = *(uint32_t*)&h23;
    lv.x = *(uint32_t*)&l01; lv.y = *(uint32_t*)&l23;
    *(uint2*)(smem + (r * ASTRIDE + k0) * 2) = hv;
    *(uint2*)(smem + A_LO + (r * ASTRIDE + k0) * 2) = lv;
}

__device__ __forceinline__ void mma_setup(uint32_t aoff[2], int lane, int warp_m) {
    const int rin = lane & 7, sel = lane >> 3;
    #pragma unroll
    for (int mt = 0; mt < 2; mt++) {
        int row = warp_m * 32 + mt * 16 + (sel & 1) * 8 + rin;
        int col = (sel >> 1) * 8;
        aoff[mt] = (uint32_t)((row * ASTRIDE + col) * 2);
    }
}

__device__ __forceinline__ void zero_acc(float acc[2][4][4]) {
    #pragma unroll
    for (int mt = 0; mt < 2; mt++)
        #pragma unroll
        for (int nt = 0; nt < 4; nt++)
            #pragma unroll
            for (int u = 0; u < 4; u++) acc[mt][nt][u] = 0.f;
}

__device__ __forceinline__ void mma_mainloop(float acc[2][4][4], const uint32_t aoff[2],
                                             uint32_t sb, const uint4* __restrict__ Bp,
                                             int warp_n, int lane) {
    const uint32_t aHi = sb, aLo = sb + A_LO;
    #pragma unroll
    for (int ks = 0; ks < 8; ks++) {
        uint32_t kb = ks * 32;
        uint32_t ah[2][4], al[2][4];
        int idx = ((warp_n * 8 + ks) * 32 + lane) * 2;
        uint4 u0 = __ldg(Bp + idx);
        uint4 u1 = __ldg(Bp + idx + 1);
        uint4 l0 = __ldg(Bp + idx + 2048);
        uint4 l1 = __ldg(Bp + idx + 2049);
        LDSM4(ah[0], aHi + aoff[0] + kb);
        LDSM4(ah[1], aHi + aoff[1] + kb);
        LDSM4(al[0], aLo + aoff[0] + kb);
        LDSM4(al[1], aLo + aoff[1] + kb);
        uint32_t bh[4][2], bl[4][2];
        bh[0][0] = u0.x; bh[0][1] = u0.y; bh[1][0] = u0.z; bh[1][1] = u0.w;
        bh[2][0] = u1.x; bh[2][1] = u1.y; bh[3][0] = u1.z; bh[3][1] = u1.w;
        bl[0][0] = l0.x; bl[0][1] = l0.y; bl[1][0] = l0.z; bl[1][1] = l0.w;
        bl[2][0] = l1.x; bl[2][1] = l1.y; bl[3][0] = l1.z; bl[3][1] = l1.w;
        #pragma unroll
        for (int mt = 0; mt < 2; mt++)
            #pragma unroll
            for (int nt = 0; nt < 4; nt++) {
                MMA16816(acc[mt][nt], ah[mt], bh[nt]);
                MMA16816(acc[mt][nt], ah[mt], bl[nt]);
                MMA16816(acc[mt][nt], al[mt], bh[nt]);
            }
    }
}

__device__ __forceinline__ void stage_c(float* Cs, const float acc[2][4][4],
                                        int lane, int warp_m, int warp_n) {
    int gid = lane >> 2, tig = lane & 3;
    #pragma unroll
    for (int mt = 0; mt < 2; mt++) {
        int r = warp_m * 32 + mt * 16 + gid;
        #pragma unroll
        for (int nt = 0; nt < 4; nt++) {
            int cc = warp_n * 32 + nt * 8 + tig * 2;
            *(float2*)&Cs[r * CSTRIDE + cc] = make_float2(acc[mt][nt][0], acc[mt][nt][1]);
            *(float2*)&Cs[(r + 8) * CSTRIDE + cc] = make_float2(acc[mt][nt][2], acc[mt][nt][3]);
        }
    }
}

// ========================= GEMM body (modes 0,1,2) ===========================
// Fragment-layout epilogue: bias + store straight from accumulators (no smem
// staging round trip, no post-mainloop barriers).
__device__ __forceinline__ void gemm_body(
        char* smem,
        const float* __restrict__ A, int M,
        const __nv_bfloat16* __restrict__ Bpack,
        const float* __restrict__ bias,
        float* __restrict__ C, int ldc, int mode,
        const float* __restrict__ gamma,
        const float* __restrict__ beta,
        float* __restrict__ aux,
        int row0, int ncoff) {
    const int tid = threadIdx.x;
    const int lane = tid & 31, wid = tid >> 5;
    const int warp_m = wid >> 2, warp_n = wid & 3;
    const uint4* Bp = (const uint4*)Bpack;
    const uint32_t sb = smem_u32(smem);

    {
        int r = tid >> 2, k0 = (tid & 3) * 32;
        int arow = row0 + r;
        bool vr = arow < M;
        const float4* src = (const float4*)(A + (size_t)arow * 128 + k0);
        float4 av[8];
        #pragma unroll
        for (int q = 0; q < 8; q++)
            av[q] = vr ? __ldg(src + q) : make_float4(0.f, 0.f, 0.f, 0.f);

        if (mode >= 1 && vr) {
            float4* dstaux = (float4*)(aux + (size_t)arow * 128 + k0);
            #pragma unroll
            for (int q = 0; q < 8; q++) dstaux[q] = av[q];
        }
        if (mode == 1) {
            float s = 0.f, s2 = 0.f;
            #pragma unroll
            for (int q = 0; q < 8; q++) {
                s  += av[q].x + av[q].y + av[q].z + av[q].w;
                s2 += av[q].x*av[q].x + av[q].y*av[q].y + av[q].z*av[q].z + av[q].w*av[q].w;
            }
            s  += __shfl_xor_sync(0xffffffffu, s, 1);
            s  += __shfl_xor_sync(0xffffffffu, s, 2);
            s2 += __shfl_xor_sync(0xffffffffu, s2, 1);
            s2 += __shfl_xor_sync(0xffffffffu, s2, 2);
            float mu = s * (1.0f / H);
            float var = s2 * (1.0f / H) - mu * mu;
            float inv = rsqrtf(var + 1e-5f);
            #pragma unroll
            for (int q = 0; q < 8; q++) {
                int k = k0 + q * 4;
                float4 gm = __ldg((const float4*)(gamma + k));
                float4 bt = __ldg((const float4*)(beta + k));
                av[q].x = (av[q].x - mu) * inv * gm.x + bt.x;
                av[q].y = (av[q].y - mu) * inv * gm.y + bt.y;
                av[q].z = (av[q].z - mu) * inv * gm.z + bt.z;
                av[q].w = (av[q].w - mu) * inv * gm.w + bt.w;
            }
        }
        #pragma unroll
        for (int q = 0; q < 8; q++)
            a_split_store(smem, r, k0 + q * 4, av[q]);
    }
    __syncthreads();

    float acc[2][4][4];
    zero_acc(acc);
    uint32_t aoff[2];
    mma_setup(aoff, lane, warp_m);
    mma_mainloop(acc, aoff, sb, Bp, warp_n, lane);

    // fragment-layout epilogue: bias + direct store
    {
        const int gid = lane >> 2, tig = lane & 3;
        #pragma unroll
        for (int mt = 0; mt < 2; mt++) {
            #pragma unroll
            for (int rg = 0; rg < 2; rg++) {
                int grow = row0 + warp_m * 32 + mt * 16 + rg * 8 + gid;
                if (grow >= M) continue;
                float* dst = C + (size_t)grow * ldc + ncoff;
                #pragma unroll
                for (int nt = 0; nt < 4; nt++) {
                    int c = warp_n * 32 + nt * 8 + tig * 2;
                    float2 o;
                    o.x = acc[mt][nt][rg * 2 + 0];
                    o.y = acc[mt][nt][rg * 2 + 1];
                    if (bias) {
                        float2 bv = __ldg((const float2*)(bias + c));
                        o.x += bv.x; o.y += bv.y;
                    }
                    *(float2*)(dst + c) = o;
                }
            }
        }
    }
}

#define GB_N  ((N_NODES + 63) / 64)       // 313
#define GB_3N ((3 * N_NODES + 63) / 64)   // 938
#define GB_E  (N_EDGES / 64)              // 5000
#define SCAT_BLKS ((N_EDGES + 255) / 256) // 1250

// ===== merged launch: csr_scatter blocks + gemmA blocks ======================
__global__ __launch_bounds__(256, 4)
void scatter_gemmA(const int* __restrict__ ei,
                   const float* __restrict__ dist,
                   const float* __restrict__ ev,
                   const float* __restrict__ node_scalar,
                   const float* __restrict__ node_vector,
                   const __nv_bfloat16* __restrict__ wpN,
                   const __nv_bfloat16* __restrict__ wpC,
                   const float* __restrict__ b_node,
                   const float* __restrict__ gamma,
                   const float* __restrict__ beta,
                   float* __restrict__ ns, float* __restrict__ nv,
                   float* __restrict__ ns1, float* __restrict__ nvec1) {
    extern __shared__ char smem[];
    int bx = blockIdx.x;
    if (bx < SCAT_BLKS) {
        int e = bx * 256 + threadIdx.x;
        if (e < N_EDGES) {
            int i = ei[e];
            int j = ei[N_EDGES + e];
            int pos = atomicAdd(&g_cur[i], 1);
            g_eids[pos] = e;
            g_own[pos] = i;
            g_ej[pos] = j;
            g_distc[pos] = dist[e];
            g_evc[pos * 3 + 0] = ev[e * 3 + 0];
            g_evc[pos * 3 + 1] = ev[e * 3 + 1];
            g_evc[pos * 3 + 2] = ev[e * 3 + 2];
        }
        return;
    }
    bx -= SCAT_BLKS;
    if (bx < GB_3N) {
        gemm_body(smem, node_vector, 3 * N_NODES, wpC, nullptr,
                  nv, 128, 2, nullptr, nullptr, nvec1, bx * 64, 0);
    } else {
        gemm_body(smem, node_scalar, N_NODES, wpN, b_node,
                  ns, 128, 1, gamma, beta, ns1, (bx - GB_3N) * 64, 0);
    }
}

// ===== combined launch B =====
__global__ __launch_bounds__(256, 4)
void gemmB(const float* __restrict__ nvec1,
           const float* __restrict__ ns1,
           const __nv_bfloat16* __restrict__ wpV,
           const __nv_bfloat16* __restrict__ wpP2,
           const float* __restrict__ b_p2,
           float* __restrict__ wv, float* __restrict__ p) {
    extern __shared__ char smem[];
    int bx = blockIdx.x;
    if (bx < GB_3N * 2) {
        int yt = bx & 1, rb = bx >> 1;
        gemm_body(smem, nvec1, 3 * N_NODES, wpV + (size_t)yt * 32768, nullptr,
                  wv, 256, 0, nullptr, nullptr, nullptr, rb * 64, yt * 128);
    } else {
        int idx = bx - GB_3N * 2;
        int yt = idx % 3, rb = idx / 3;
        gemm_body(smem, ns1, N_NODES, wpP2 + (size_t)yt * 32768, b_p2 + yt * 128,
                  p, 384, 0, nullptr, nullptr, nullptr, rb * 64, yt * 128);
    }
}

// ========================= MEGA message + edge-final (3 CTAs/SM) =============
__global__ __launch_bounds__(256, 3)
void mega_msg(const float* __restrict__ efeat,
              const __nv_bfloat16* __restrict__ Wedge,
              const __nv_bfloat16* __restrict__ Wp1,
              const __nv_bfloat16* __restrict__ Wf,
              const float* __restrict__ b_edge,
              const float* __restrict__ b_p1,
              const float* __restrict__ b_f,
              const int* __restrict__ eids,
              const int* __restrict__ own,
              const int* __restrict__ ejArr,
              const float* __restrict__ distc,
              const float* __restrict__ alpha,
              const float* __restrict__ evc,
              const float* __restrict__ ns,
              const float* __restrict__ nvec,
              const float* __restrict__ nv_cross,
              float* __restrict__ ns1,
              float* __restrict__ nvec1,
              float* __restrict__ out_edge) {
    extern __shared__ char smem[];
    const int tid = threadIdx.x;
    const int lane = tid & 31, wid = tid >> 5;
    const int warp_m = wid >> 2, warp_n = wid & 3;
    const int row0 = blockIdx.x * 64;
    const uint32_t sb = smem_u32(smem);
    const uint4* BpE = (const uint4*)Wedge;
    const uint4* Bp1a = (const uint4*)Wp1;
    const uint4* Bp1b = (const uint4*)(Wp1 + 32768);
    const uint4* BpF = (const uint4*)Wf;

    float* Cs0 = (float*)(smem + 34816);
    float* As  = (float*)smem;
    int* sOwn = (int*)(smem + 68608);
    int* sEj  = (int*)(smem + 68864);
    int* sEid = (int*)(smem + 69120);
    float* sEv = (float*)(smem + 69376);

    // Phase A: gathered edge_feats rows (streaming), split; meta
    {
        int r = tid >> 2, k0 = (tid & 3) * 32;
        int e = eids[row0 + r];
        const float4* src = (const float4*)(efeat + (size_t)e * 128 + k0);
        float4 av[8];
        #pragma unroll
        for (int q = 0; q < 8; q++) av[q] = __ldcs(src + q);
        #pragma unroll
        for (int q = 0; q < 8; q++) a_split_store(smem, r, k0 + q * 4, av[q]);
    }
    if (tid < 64) {
        sOwn[tid] = own[row0 + tid];
        sEj[tid]  = ejArr[row0 + tid];
        sEid[tid] = eids[row0 + tid];
        sEv[tid * 3 + 0] = evc[(row0 + tid) * 3 + 0];
        sEv[tid * 3 + 1] = evc[(row0 + tid) * 3 + 1];
        sEv[tid * 3 + 2] = evc[(row0 + tid) * 3 + 2];
    }
    __syncthreads();

    uint32_t aoff[2];
    mma_setup(aoff, lane, warp_m);

    // Phase B: ef GEMM (W_edge) + fragment-layout msg epilogue
    float acc[2][4][4];
    zero_acc(acc);
    mma_mainloop(acc, aoff, sb, BpE, warp_n, lane);
    {
        const int gid = lane >> 2, tig = lane & 3;
        #pragma unroll
        for (int mt = 0; mt < 2; mt++) {
            #pragma unroll
            for (int rg = 0; rg < 2; rg++) {
                int r = warp_m * 32 + mt * 16 + rg * 8 + gid;
                int ii = sOwn[r], jj = sEj[r];
                float dd = __ldg(distc + row0 + r);
                float cut = (dd < CUTOFF_R) ? 0.5f * (__cosf(PI_F * dd / CUTOFF_R) + 1.0f) : 0.0f;
                float efv[4][2], nsjv[4][2];
                float h0 = 0.f, h1 = 0.f;
                #pragma unroll
                for (int nt = 0; nt < 4; nt++) {
                    int c = warp_n * 32 + nt * 8 + tig * 2;
                    float2 be = __ldg((const float2*)(b_edge + c));
                    float2 al = __ldg((const float2*)(alpha + c));
                    float2 ni = __ldg((const float2*)(ns + (size_t)ii * H + c));
                    float2 nj = __ldg((const float2*)(ns + (size_t)jj * H + c));
                    float e0 = silu_f(acc[mt][nt][rg * 2 + 0] + be.x);
                    float e1 = silu_f(acc[mt][nt][rg * 2 + 1] + be.y);
                    efv[nt][0] = e0; efv[nt][1] = e1;
                    nsjv[nt][0] = nj.x; nsjv[nt][1] = nj.y;
                    float t0 = silu_f(ni.x + nj.x + e0) * al.x;
                    float t1 = silu_f(ni.y + nj.y + e1) * al.y;
                    if (nt < 2) h0 += t0 + t1; else h1 += t0 + t1;
                }
                h0 += __shfl_xor_sync(0xffffffffu, h0, 1);
                h0 += __shfl_xor_sync(0xffffffffu, h0, 2);
                h1 += __shfl_xor_sync(0xffffffffu, h1, 1);
                h1 += __shfl_xor_sync(0xffffffffu, h1, 2);
                float attn0 = h0 * cut, attn1 = h1 * cut;
                #pragma unroll
                for (int nt = 0; nt < 4; nt++) {
                    int c = warp_n * 32 + nt * 8 + tig * 2;
                    float a = (nt < 2) ? attn0 : attn1;
                    float2 m;
                    m.x = nsjv[nt][0] * efv[nt][0] * a;
                    m.y = nsjv[nt][1] * efv[nt][1] * a;
                    *(float2*)&Cs0[r * CSTRIDE + c] = m;
                }
            }
        }
    }
    __syncthreads();

    // Phase Wf: GEMM (A still holds efeat) + edge-final epilogue in FRAGMENT layout
    zero_acc(acc);
    mma_mainloop(acc, aoff, sb, BpF, warp_n, lane);
    {
        const int gid = lane >> 2, tig = lane & 3;
        #pragma unroll
        for (int mt = 0; mt < 2; mt++) {
            #pragma unroll
            for (int rg = 0; rg < 2; rg++) {
                int r = warp_m * 32 + mt * 16 + rg * 8 + gid;
                int ii = sOwn[r], jj = sEj[r], eorig = sEid[r];
                float v0 = sEv[r * 3 + 0], v1 = sEv[r * 3 + 1], v2 = sEv[r * 3 + 2];
                float vvq = v0 * v0 + v1 * v1 + v2 * v2;
                const float* arow = nv_cross + (size_t)ii * 384;
                const float* brow = nv_cross + (size_t)jj * 384;
                float* dst = out_edge + (size_t)eorig * H;
                #pragma unroll
                for (int nt = 0; nt < 4; nt++) {
                    int c = warp_n * 32 + nt * 8 + tig * 2;
                    float d0 = acc[mt][nt][rg * 2 + 0] + __ldg(b_f + c);
                    float d1 = acc[mt][nt][rg * 2 + 1] + __ldg(b_f + c + 1);
                    uint32_t h2 = *(uint32_t*)(smem + (r * ASTRIDE + c) * 2);
                    uint32_t l2 = *(uint32_t*)(smem + A_LO + (r * ASTRIDE + c) * 2);
                    float2 hf = __bfloat1622float2(*(__nv_bfloat162*)&h2);
                    float2 lf = __bfloat1622float2(*(__nv_bfloat162*)&l2);
                    float2 a0 = __ldg((const float2*)(arow + c));
                    float2 a1 = __ldg((const float2*)(arow + 128 + c));
                    float2 a2 = __ldg((const float2*)(arow + 256 + c));
                    float2 b0 = __ldg((const float2*)(brow + c));
                    float2 b1 = __ldg((const float2*)(brow + 128 + c));
                    float2 b2 = __ldg((const float2*)(brow + 256 + c));
                    float ab0 = a0.x * b0.x + a1.x * b1.x + a2.x * b2.x;
                    float av0 = a0.x * v0 + a1.x * v1 + a2.x * v2;
                    float bv0 = b0.x * v0 + b1.x * v1 + b2.x * v2;
                    float ab1 = a0.y * b0.y + a1.y * b1.y + a2.y * b2.y;
                    float av1 = a0.y * v0 + a1.y * v1 + a2.y * v2;
                    float bv1 = b0.y * v0 + b1.y * v1 + b2.y * v2;
                    float2 o;
                    o.x = (hf.x + lf.x) + silu_f(d0) * (ab0 * vvq - av0 * bv0);
                    o.y = (hf.y + lf.y) + silu_f(d1) * (ab1 * vvq - av1 * bv1);
                    __stcs((float2*)(dst + c), o);
                }
            }
        }
    }

    // Phase D: scalar agg walk (col-pair x quarter; 16-iter chains)
    {
        int qp = tid & 63, hf = tid >> 6;
        int rbeg = hf * 16, rend = rbeg + 16;
        int c0 = qp * 2;
        float a0 = 0.f, a1 = 0.f;
        int prev = sOwn[rbeg];
        #pragma unroll 4
        for (int r2 = rbeg; r2 < rend; r2++) {
            int o = sOwn[r2];
            float2 v = *(float2*)&Cs0[r2 * CSTRIDE + c0];
            if (o != prev) {
                atomicAdd(&ns1[(size_t)prev * H + c0], a0);
                atomicAdd(&ns1[(size_t)prev * H + c0 + 1], a1);
                a0 = a1 = 0.f; prev = o;
            }
            a0 += v.x; a1 += v.y;
        }
        atomicAdd(&ns1[(size_t)prev * H + c0], a0);
        atomicAdd(&ns1[(size_t)prev * H + c0 + 1], a1);
    }
    __syncthreads();   // all A reads (Wf epi) + Cs0 reads done

    // Phase E: re-split msg (Cs0) into bf16 A region
    {
        int r = tid >> 2, k0 = (tid & 3) * 32;
        #pragma unroll
        for (int q = 0; q < 8; q++) {
            int k = k0 + q * 4;
            float4 a = make_float4(Cs0[r * CSTRIDE + k], Cs0[r * CSTRIDE + k + 1],
                                   Cs0[r * CSTRIDE + k + 2], Cs0[r * CSTRIDE + k + 3]);
            a_split_store(smem, r, k0 + q * 4, a);
        }
    }
    __syncthreads();

    // Phase F: Wp1 pass a -> stage s1 into Cs0 (msg dead)
    zero_acc(acc);
    mma_mainloop(acc, aoff, sb, Bp1a, warp_n, lane);
    stage_c(Cs0, acc, lane, warp_m, warp_n);

    // Phase G: Wp1 pass b
    zero_acc(acc);
    mma_mainloop(acc, aoff, sb, Bp1b, warp_n, lane);
    __syncthreads();   // all A reads done (pass b), s1 writes visible
    stage_c(As, acc, lane, warp_m, warp_n);   // s2 over dead A region
    __syncthreads();

    // Phase I: vmsg walk (s1 in Cs0, s2 in As)
    {
        const int qp = tid & 63, hf = tid >> 6;
        const int rbeg = hf * 16, rend = rbeg + 16;
        const int c0 = qp * 2;
        float2 b1 = __ldg((const float2*)(b_p1 + c0));
        float2 b2 = __ldg((const float2*)(b_p1 + 128 + c0));
        float a00 = 0.f, a01 = 0.f, a10 = 0.f, a11 = 0.f, a20 = 0.f, a21 = 0.f;
        int prev = sOwn[rbeg];
        #pragma unroll 4
        for (int r2 = rbeg; r2 < rend; r2++) {
            int o = sOwn[r2];
            int j = sEj[r2];
            float2 s1v = *(float2*)&Cs0[r2 * CSTRIDE + c0];
            float2 s2v = *(float2*)&As[r2 * CSTRIDE + c0];
            float s1a = silu_f(s1v.x + b1.x), s1b = silu_f(s1v.y + b1.y);
            float s2a = silu_f(s2v.x + b2.x), s2b = silu_f(s2v.y + b2.y);
            const float* nv = nvec + (size_t)j * 384 + c0;
            float2 n0 = __ldg((const float2*)nv);
            float2 n1 = __ldg((const float2*)(nv + 128));
            float2 n2 = __ldg((const float2*)(nv + 256));
            float e0 = sEv[r2 * 3 + 0], e1 = sEv[r2 * 3 + 1], e2 = sEv[r2 * 3 + 2];
            if (o != prev) {
                atomicAdd(&nvec1[(size_t)prev * 384 + c0], a00);
                atomicAdd(&nvec1[(size_t)prev * 384 + c0 + 1], a01);
                atomicAdd(&nvec1[(size_t)prev * 384 + 128 + c0], a10);
                atomicAdd(&nvec1[(size_t)prev * 384 + 128 + c0 + 1], a11);
                atomicAdd(&nvec1[(size_t)prev * 384 + 256 + c0], a20);
                atomicAdd(&nvec1[(size_t)prev * 384 + 256 + c0 + 1], a21);
                a00 = a01 = a10 = a11 = a20 = a21 = 0.f; prev = o;
            }
            a00 = fmaf(n0.x, s1a, fmaf(s2a, e0, a00));
            a01 = fmaf(n0.y, s1b, fmaf(s2b, e0, a01));
            a10 = fmaf(n1.x, s1a, fmaf(s2a, e1, a10));
            a11 = fmaf(n1.y, s1b, fmaf(s2b, e1, a11));
            a20 = fmaf(n2.x, s1a, fmaf(s2a, e2, a20));
            a21 = fmaf(n2.y, s1b, fmaf(s2b, e2, a21));
        }
        atomicAdd(&nvec1[(size_t)prev * 384 + c0], a00);
        atomicAdd(&nvec1[(size_t)prev * 384 + c0 + 1], a01);
        atomicAdd(&nvec1[(size_t)prev * 384 + 128 + c0], a10);
        atomicAdd(&nvec1[(size_t)prev * 384 + 128 + c0 + 1], a11);
        atomicAdd(&nvec1[(size_t)prev * 384 + 256 + c0], a20);
        atomicAdd(&nvec1[(size_t)prev * 384 + 256 + c0 + 1], a21);
    }
}

// ========================= node final =========================
__global__ void node_final(float* __restrict__ out_scal,
                           float* __restrict__ out_vec) {
    int n = blockIdx.x;
    int h = threadIdx.x;
    float v1d[3], v2d[3];
    #pragma unroll
    for (int d = 0; d < 3; d++) {
        v1d[d] = g_wv[((size_t)n * 3 + d) * 256 + h];
        v2d[d] = g_wv[((size_t)n * 3 + d) * 256 + 128 + h];
    }
    float tri = v1d[0] * v2d[0] + v1d[1] * v2d[1] + v1d[2] * v2d[2];
    float sq  = v2d[0] * v2d[0] + v2d[1] * v2d[1] + v2d[2] * v2d[2];
    float nrm = sqrtf(sq + 1e-8f);
    float qua = nrm * nrm * nrm;
    float p1 = g_p[(size_t)n * 384 + h];
    float p2 = g_p[(size_t)n * 384 + 128 + h];
    float p3 = g_p[(size_t)n * 384 + 256 + h];
    out_scal[(size_t)n * H + h] = g_ns1[(size_t)n * H + h] + (qua + tri) * p1 + p2;
    #pragma unroll
    for (int d = 0; d < 3; d++) {
        out_vec[((size_t)n * 3 + d) * H + h] =
            g_nvec1[((size_t)n * 3 + d) * H + h] + v1d[d] * p3;
    }
}

// ========================= launch =========================
extern "C" void kernel_launch(void* const* d_in, const int* in_sizes, int n_in,
                              void* d_out, int out_size) {
    const float* node_scalar = (const float*)d_in[0];
    const float* node_vector = (const float*)d_in[1];
    const int*   edge_index  = (const int*)  d_in[2];
    const float* dist        = (const float*)d_in[3];
    const float* edge_feats  = (const float*)d_in[4];
    const float* edge_vector = (const float*)d_in[5];
    const float* ln_gamma    = (const float*)d_in[6];
    const float* ln_beta     = (const float*)d_in[7];
    const float* alpha       = (const float*)d_in[8];
    const float* W_cross     = (const float*)d_in[9];
    const float* W_node      = (const float*)d_in[10];
    const float* b_node      = (const float*)d_in[11];
    const float* W_edge      = (const float*)d_in[12];
    const float* b_edge      = (const float*)d_in[13];
    const float* W_p1        = (const float*)d_in[14];
    const float* b_p1        = (const float*)d_in[15];
    const float* W_p2        = (const float*)d_in[16];
    const float* b_p2        = (const float*)d_in[17];
    const float* W_vec       = (const float*)d_in[18];
    const float* W_f         = (const float*)d_in[19];
    const float* b_f         = (const float*)d_in[20];

    float* out = (float*)d_out;
    float* out_scal = out;
    float* out_vec  = out + (size_t)N_NODES * H;
    float* out_edge = out + (size_t)N_NODES * H * 4;

    float* p_ns;    cudaGetSymbolAddress((void**)&p_ns, g_ns);
    float* p_nv;    cudaGetSymbolAddress((void**)&p_nv, g_nv);
    float* p_ns1;   cudaGetSymbolAddress((void**)&p_ns1, g_ns1);
    float* p_nvec1; cudaGetSymbolAddress((void**)&p_nvec1, g_nvec1);
    float* p_wv;    cudaGetSymbolAddress((void**)&p_wv, g_wv);
    float* p_p;     cudaGetSymbolAddress((void**)&p_p, g_p);
    __nv_bfloat16* wp; cudaGetSymbolAddress((void**)&wp, g_wpack);
    int* p_eids;  cudaGetSymbolAddress((void**)&p_eids, g_eids);
    int* p_own;   cudaGetSymbolAddress((void**)&p_own, g_own);
    int* p_ej;    cudaGetSymbolAddress((void**)&p_ej, g_ej);
    float* p_distc; cudaGetSymbolAddress((void**)&p_distc, g_distc);
    float* p_evc;   cudaGetSymbolAddress((void**)&p_evc, g_evc);

    cudaFuncSetAttribute(scatter_gemmA, cudaFuncAttributeMaxDynamicSharedMemorySize, SM_GEMM);
    cudaFuncSetAttribute(gemmB, cudaFuncAttributeMaxDynamicSharedMemorySize, SM_GEMM);
    cudaFuncSetAttribute(mega_msg, cudaFuncAttributeMaxDynamicSharedMemorySize, SM_MEGA);

    // 1: weight pack + distributed edge histogram (22 blocks)
    pack_hist<<<22, 1024>>>(W_node, W_edge, W_p1, W_cross, W_f, W_vec, W_p2, edge_index);
    // 2: scan (1 block, self-cleans g_deg)
    csr_scan<<<1, 1024>>>();
    // 3: csr_scatter + gemmA (merged)
    scatter_gemmA<<<SCAT_BLKS + GB_3N + GB_N, 256, SM_GEMM>>>(
        edge_index, dist, edge_vector,
        node_scalar, node_vector, wp + 0 * 32768, wp + 4 * 32768,
        b_node, ln_gamma, ln_beta, p_ns, p_nv, p_ns1, p_nvec1);
    // 4: message path + edge update (fragment-layout epilogues)
    mega_msg<<<GB_E, 256, SM_MEGA>>>(edge_feats, wp + 1 * 32768, wp + 2 * 32768, wp + 5 * 32768,
                                     b_edge, b_p1, b_f, p_eids, p_own, p_ej, p_distc,
                                     alpha, p_evc, p_ns, node_vector, p_nv,
                                     p_ns1, p_nvec1, out_edge);
    // 5: wv + p (combined, fragment-layout epilogue)
    gemmB<<<GB_3N * 2 + GB_N * 3, 256, SM_GEMM>>>(p_nvec1, p_ns1,
                                                  wp + 6 * 32768, wp + 8 * 32768,
                                                  b_p2, p_wv, p_p);
    // 6
    node_final<<<N_NODES, 128>>>(out_scal, out_vec);
}